// round 14
// baseline (speedup 1.0000x reference)
#include <cuda_runtime.h>
#include <cuda_bf16.h>
#include <cstdint>

// Problem constants
#define BB   4
#define CCH  256
#define NPX  4096     // W*H = 64*64
#define CQ   64       // C/4

#define OUT_ELEMS  ((size_t)BB * CCH * NPX)          // 4,194,304
#define ATTN_ELEMS ((size_t)BB * NPX * NPX)          // 67,108,864

// Scratch: pre-split bf16 Q/K stored [b][n][cq]; bf16 x [b][c][n]; bf16 attn
__device__ __nv_bfloat16 g_Qh[BB * NPX * CQ];
__device__ __nv_bfloat16 g_Ql[BB * NPX * CQ];
__device__ __nv_bfloat16 g_Kh[BB * NPX * CQ];
__device__ __nv_bfloat16 g_Kl[BB * NPX * CQ];
__device__ __nv_bfloat16 g_Xb[BB * CCH * NPX];
__device__ __nv_bfloat16 g_attn_b[ATTN_ELEMS];
// Fallback attention buffer in case d_out only holds `out`
__device__ float g_attn_fb[ATTN_ELEMS];

// ===========================================================================
// Helpers (base sm_100-legal: ldmatrix + mma.sync + cp.async)
// ===========================================================================
__device__ __forceinline__ uint32_t smem_u32(const void* p) {
    uint32_t a;
    asm("{ .reg .u64 t; cvta.to.shared.u64 t, %1; cvt.u32.u64 %0, t; }"
        : "=r"(a) : "l"(p));
    return a;
}
// Pack two f32 into bf16x2 {lo, hi}. Single SASS op.
__device__ __forceinline__ uint32_t pack_bf16x2(float lo, float hi) {
    uint32_t r;
    asm("cvt.rn.bf16x2.f32 %0, %1, %2;" : "=r"(r) : "f"(hi), "f"(lo));
    return r;
}
__device__ __forceinline__ void ldmatrix_x4(uint32_t& r0, uint32_t& r1,
                                            uint32_t& r2, uint32_t& r3,
                                            uint32_t addr) {
    asm volatile("ldmatrix.sync.aligned.m8n8.x4.shared.b16 {%0,%1,%2,%3}, [%4];"
                 : "=r"(r0), "=r"(r1), "=r"(r2), "=r"(r3) : "r"(addr));
}
__device__ __forceinline__ void mma_16816(float* c, uint32_t a0, uint32_t a1,
                                          uint32_t a2, uint32_t a3,
                                          uint32_t b0, uint32_t b1) {
    asm volatile(
        "mma.sync.aligned.m16n8k16.row.col.f32.bf16.bf16.f32 "
        "{%0,%1,%2,%3}, {%4,%5,%6,%7}, {%8,%9}, {%0,%1,%2,%3};"
        : "+f"(c[0]), "+f"(c[1]), "+f"(c[2]), "+f"(c[3])
        : "r"(a0), "r"(a1), "r"(a2), "r"(a3), "r"(b0), "r"(b1));
}
__device__ __forceinline__ void cp_async16(uint32_t smem_addr, const void* gptr) {
    asm volatile("cp.async.cg.shared.global [%0], [%1], 16;"
                 :: "r"(smem_addr), "l"(gptr));
}
#define CP_COMMIT() asm volatile("cp.async.commit_group;")
#define CP_WAIT0()  asm volatile("cp.async.wait_group 0;")
#define CP_WAIT1()  asm volatile("cp.async.wait_group 1;")
#define CP_WAIT2()  asm volatile("cp.async.wait_group 2;")

// 64B-pitch swizzle (16B units 0..3)
__device__ __forceinline__ uint32_t swz16(int row, int unit) {
    return (uint32_t)row * 64 + (((uint32_t)unit ^ (((uint32_t)row >> 1) & 3u)) * 16);
}
// 128B-pitch swizzle (16B units 0..7)
__device__ __forceinline__ uint32_t swz128(int row, int unit) {
    return (uint32_t)row * 128 + (((uint32_t)unit ^ ((uint32_t)row & 7u)) * 16);
}

// ---------------------------------------------------------------------------
// Kernel 0: x -> bf16 copy
// ---------------------------------------------------------------------------
__global__ void xconv_kernel(const float* __restrict__ x, __nv_bfloat16* __restrict__ xb)
{
    const size_t n4 = OUT_ELEMS / 4;
    for (size_t i = (size_t)blockIdx.x * blockDim.x + threadIdx.x; i < n4;
         i += (size_t)gridDim.x * blockDim.x) {
        float4 v = *(const float4*)(x + i * 4);
        *(uint2*)(xb + i * 4) = make_uint2(pack_bf16x2(v.x, v.y),
                                           pack_bf16x2(v.z, v.w));
    }
}

// ---------------------------------------------------------------------------
// Kernel 1: fused Q+K projection + hi/lo split (shared x tile).
// ---------------------------------------------------------------------------
__global__ void proj2_kernel(const float* __restrict__ x,
                             const float* __restrict__ wq,
                             const float* __restrict__ bq,
                             const float* __restrict__ wk,
                             const float* __restrict__ bk,
                             __nv_bfloat16* __restrict__ qH,
                             __nv_bfloat16* __restrict__ qL,
                             __nv_bfloat16* __restrict__ kH,
                             __nv_bfloat16* __restrict__ kL)
{
    const int b  = blockIdx.y;
    const int n0 = blockIdx.x * 64;
    const int tid = threadIdx.x;
    const int tx = tid & 15;        // n dimension
    const int ty = tid >> 4;        // oc dimension

    __shared__ __align__(16) float Xs[32][64];    // [c][n]
    __shared__ __align__(16) float Wq[32][68];    // [c][oc]
    __shared__ __align__(16) float Wk[32][68];    // [c][oc]

    const float* xb = x + (size_t)b * CCH * NPX;

    float aq[4][4], ak[4][4];
#pragma unroll
    for (int i = 0; i < 4; i++)
#pragma unroll
        for (int j = 0; j < 4; j++) { aq[i][j] = 0.f; ak[i][j] = 0.f; }

    for (int c0 = 0; c0 < CCH; c0 += 32) {
#pragma unroll
        for (int r = 0; r < 2; r++) {
            int idx = tid + r * 256;
            int cc  = idx >> 4;
            int nq  = (idx & 15) << 2;
            float4 v = *(const float4*)(xb + (size_t)(c0 + cc) * NPX + n0 + nq);
            *(float4*)(&Xs[cc][nq]) = v;
        }
#pragma unroll
        for (int r = 0; r < 2; r++) {
            int idx = tid + r * 256;
            int oc  = idx >> 3;
            int cq  = (idx & 7) << 2;
            float4 v = *(const float4*)(wq + oc * CCH + c0 + cq);
            Wq[cq + 0][oc] = v.x; Wq[cq + 1][oc] = v.y;
            Wq[cq + 2][oc] = v.z; Wq[cq + 3][oc] = v.w;
            float4 u = *(const float4*)(wk + oc * CCH + c0 + cq);
            Wk[cq + 0][oc] = u.x; Wk[cq + 1][oc] = u.y;
            Wk[cq + 2][oc] = u.z; Wk[cq + 3][oc] = u.w;
        }
        __syncthreads();
#pragma unroll
        for (int cc = 0; cc < 32; cc++) {
            float4 q4 = *(const float4*)(&Wq[cc][ty * 4]);
            float4 k4 = *(const float4*)(&Wk[cc][ty * 4]);
            float4 bv = *(const float4*)(&Xs[cc][tx * 4]);
            float qv[4] = {q4.x, q4.y, q4.z, q4.w};
            float kv[4] = {k4.x, k4.y, k4.z, k4.w};
            float bw[4] = {bv.x, bv.y, bv.z, bv.w};
#pragma unroll
            for (int i = 0; i < 4; i++)
#pragma unroll
                for (int j = 0; j < 4; j++) {
                    aq[i][j] = fmaf(qv[i], bw[j], aq[i][j]);
                    ak[i][j] = fmaf(kv[i], bw[j], ak[i][j]);
                }
        }
        __syncthreads();
    }

    float4 bqv = *(const float4*)(bq + ty * 4);
    float4 bkv = *(const float4*)(bk + ty * 4);
    float bq4[4] = {bqv.x, bqv.y, bqv.z, bqv.w};
    float bk4[4] = {bkv.x, bkv.y, bkv.z, bkv.w};
    const size_t ob = (size_t)b * NPX * CQ;
#pragma unroll
    for (int j = 0; j < 4; j++) {
        const int n = n0 + tx * 4 + j;
        const size_t ofs = ob + (size_t)n * CQ + ty * 4;
        {
            float v0 = aq[0][j] + bq4[0], v1 = aq[1][j] + bq4[1];
            float v2 = aq[2][j] + bq4[2], v3 = aq[3][j] + bq4[3];
            float h0 = __bfloat162float(__float2bfloat16(v0));
            float h1 = __bfloat162float(__float2bfloat16(v1));
            float h2 = __bfloat162float(__float2bfloat16(v2));
            float h3 = __bfloat162float(__float2bfloat16(v3));
            *(uint2*)(qH + ofs) = make_uint2(pack_bf16x2(h0, h1), pack_bf16x2(h2, h3));
            *(uint2*)(qL + ofs) = make_uint2(pack_bf16x2(v0 - h0, v1 - h1),
                                             pack_bf16x2(v2 - h2, v3 - h3));
        }
        {
            float v0 = ak[0][j] + bk4[0], v1 = ak[1][j] + bk4[1];
            float v2 = ak[2][j] + bk4[2], v3 = ak[3][j] + bk4[3];
            float h0 = __bfloat162float(__float2bfloat16(v0));
            float h1 = __bfloat162float(__float2bfloat16(v1));
            float h2 = __bfloat162float(__float2bfloat16(v2));
            float h3 = __bfloat162float(__float2bfloat16(v3));
            *(uint2*)(kH + ofs) = make_uint2(pack_bf16x2(h0, h1), pack_bf16x2(h2, h3));
            *(uint2*)(kL + ofs) = make_uint2(pack_bf16x2(v0 - h0, v1 - h1),
                                             pack_bf16x2(v2 - h2, v3 - h3));
        }
    }
}

// ---------------------------------------------------------------------------
// Kernel 2 (tensor cores, pre-split bf16): E[i][j] = qh*kh + qh*kl + ql*kh
// CTA tile 128x128, FULL K=64 resident. Strip version: i covers 8 tiles.
// ---------------------------------------------------------------------------
#define E_MAT   (128 * 128)          // 16 KB per matrix
#define E_SMEM  (4 * E_MAT)          // 64 KB

__global__ void __launch_bounds__(256, 2) energy_mma_kernel(float* __restrict__ E,
                                                            int b, int i_base)
{
    extern __shared__ __align__(128) uint8_t es[];

    const int i0 = (i_base + blockIdx.y) * 128;
    const int j0 = blockIdx.x * 128;
    const int tid = threadIdx.x;
    const int lane = tid & 31;
    const int wid = tid >> 5;
    const int warp_m = (wid & 1) * 64;      // 2 M groups of 64
    const int warp_n = (wid >> 1) * 32;     // 4 N groups of 32

    const __nv_bfloat16* Qh = g_Qh + (size_t)b * NPX * CQ;
    const __nv_bfloat16* Ql = g_Ql + (size_t)b * NPX * CQ;
    const __nv_bfloat16* Kh = g_Kh + (size_t)b * NPX * CQ;
    const __nv_bfloat16* Kl = g_Kl + (size_t)b * NPX * CQ;

    const uint32_t qh_u = smem_u32(es);
    const uint32_t ql_u = qh_u + E_MAT;
    const uint32_t kh_u = qh_u + 2 * E_MAT;
    const uint32_t kl_u = qh_u + 3 * E_MAT;

#pragma unroll
    for (int c = 0; c < 2; c++) {
#pragma unroll
        for (int i = 0; i < 2; i++) {
            const int idx = tid + i * 256;            // 0..511
            const int row = idx >> 2;                 // 0..127
            const int u   = (idx & 3) + c * 4;        // 16B unit 0..7
            const uint32_t off = swz128(row, u);
            const size_t qo = (size_t)(i0 + row) * CQ + u * 8;
            const size_t ko = (size_t)(j0 + row) * CQ + u * 8;
            cp_async16(qh_u + off, Qh + qo);
            cp_async16(ql_u + off, Ql + qo);
            cp_async16(kh_u + off, Kh + ko);
            cp_async16(kl_u + off, Kl + ko);
        }
        CP_COMMIT();
    }

    float acc[4][4][4];
#pragma unroll
    for (int mi = 0; mi < 4; mi++)
#pragma unroll
        for (int ni = 0; ni < 4; ni++)
#pragma unroll
            for (int q = 0; q < 4; q++) acc[mi][ni][q] = 0.f;

    CP_WAIT1();
    __syncthreads();

#pragma unroll
    for (int ks = 0; ks < 4; ks++) {
        if (ks == 2) {
            CP_WAIT0();
            __syncthreads();
        }
        uint32_t ah[4][4];
#pragma unroll
        for (int mi = 0; mi < 4; mi++) {
            const int row = warp_m + mi * 16 + (lane & 7) + ((lane >> 3) & 1) * 8;
            const int u = ks * 2 + (lane >> 4);
            ldmatrix_x4(ah[mi][0], ah[mi][1], ah[mi][2], ah[mi][3],
                        qh_u + swz128(row, u));
        }
        uint32_t bh[4][2], bl[4][2];
#pragma unroll
        for (int ng = 0; ng < 2; ng++) {
            const int row = warp_n + ng * 16 + (lane & 7) + ((lane >> 4) & 1) * 8;
            const int u = ks * 2 + ((lane >> 3) & 1);
            uint32_t r0, r1, r2, r3;
            ldmatrix_x4(r0, r1, r2, r3, kh_u + swz128(row, u));
            bh[ng * 2 + 0][0] = r0; bh[ng * 2 + 0][1] = r1;
            bh[ng * 2 + 1][0] = r2; bh[ng * 2 + 1][1] = r3;
            ldmatrix_x4(r0, r1, r2, r3, kl_u + swz128(row, u));
            bl[ng * 2 + 0][0] = r0; bl[ng * 2 + 0][1] = r1;
            bl[ng * 2 + 1][0] = r2; bl[ng * 2 + 1][1] = r3;
        }
#pragma unroll
        for (int mi = 0; mi < 4; mi++)
#pragma unroll
            for (int ni = 0; ni < 4; ni++) {
                mma_16816(acc[mi][ni], ah[mi][0], ah[mi][1], ah[mi][2], ah[mi][3],
                          bh[ni][0], bh[ni][1]);
                mma_16816(acc[mi][ni], ah[mi][0], ah[mi][1], ah[mi][2], ah[mi][3],
                          bl[ni][0], bl[ni][1]);
            }
        uint32_t al[4][4];
#pragma unroll
        for (int mi = 0; mi < 4; mi++) {
            const int row = warp_m + mi * 16 + (lane & 7) + ((lane >> 3) & 1) * 8;
            const int u = ks * 2 + (lane >> 4);
            ldmatrix_x4(al[mi][0], al[mi][1], al[mi][2], al[mi][3],
                        ql_u + swz128(row, u));
        }
#pragma unroll
        for (int mi = 0; mi < 4; mi++)
#pragma unroll
            for (int ni = 0; ni < 4; ni++)
                mma_16816(acc[mi][ni], al[mi][0], al[mi][1], al[mi][2], al[mi][3],
                          bh[ni][0], bh[ni][1]);
    }

    float* Eb = E + (size_t)b * NPX * NPX;
#pragma unroll
    for (int mi = 0; mi < 4; mi++) {
        const int r0 = i0 + warp_m + mi * 16 + (lane >> 2);
#pragma unroll
        for (int ni = 0; ni < 4; ni++) {
            const int j = j0 + warp_n + ni * 8 + (lane & 3) * 2;
            *(float2*)(Eb + (size_t)r0 * NPX + j) =
                make_float2(acc[mi][ni][0], acc[mi][ni][1]);
            *(float2*)(Eb + (size_t)(r0 + 8) * NPX + j) =
                make_float2(acc[mi][ni][2], acc[mi][ni][3]);
        }
    }
}

// ---------------------------------------------------------------------------
// Kernel 3: row softmax in place + bf16 copy. One block per row (strip).
// ---------------------------------------------------------------------------
__global__ void softmax_kernel(float* __restrict__ attn,
                               __nv_bfloat16* __restrict__ attn_b)
{
    __shared__ float red[8];
    const size_t row = blockIdx.x;
    float* r = attn + row * NPX;
    __nv_bfloat16* rb = attn_b + row * NPX;
    const int t = threadIdx.x;
    const int lane = t & 31;
    const int warp = t >> 5;

    float4 v[4];
#pragma unroll
    for (int u = 0; u < 4; u++)
        v[u] = *(const float4*)(r + (size_t)(t + u * 256) * 4);

    float mx = -3.402823e38f;
#pragma unroll
    for (int u = 0; u < 4; u++)
        mx = fmaxf(mx, fmaxf(fmaxf(v[u].x, v[u].y), fmaxf(v[u].z, v[u].w)));
#pragma unroll
    for (int o = 16; o > 0; o >>= 1)
        mx = fmaxf(mx, __shfl_xor_sync(0xFFFFFFFFu, mx, o));
    if (lane == 0) red[warp] = mx;
    __syncthreads();
    float rowmax = red[0];
#pragma unroll
    for (int u = 1; u < 8; u++) rowmax = fmaxf(rowmax, red[u]);
    __syncthreads();

    float s = 0.f;
#pragma unroll
    for (int u = 0; u < 4; u++) {
        v[u].x = __expf(v[u].x - rowmax);
        v[u].y = __expf(v[u].y - rowmax);
        v[u].z = __expf(v[u].z - rowmax);
        v[u].w = __expf(v[u].w - rowmax);
        s += v[u].x + v[u].y + v[u].z + v[u].w;
    }
#pragma unroll
    for (int o = 16; o > 0; o >>= 1)
        s += __shfl_xor_sync(0xFFFFFFFFu, s, o);
    if (lane == 0) red[warp] = s;
    __syncthreads();
    float total = 0.f;
#pragma unroll
    for (int u = 0; u < 8; u++) total += red[u];
    float inv = 1.0f / total;

#pragma unroll
    for (int u = 0; u < 4; u++) {
        v[u].x *= inv; v[u].y *= inv; v[u].z *= inv; v[u].w *= inv;
        *(float4*)(r + (size_t)(t + u * 256) * 4) = v[u];
        *(uint2*)(rb + (size_t)(t + u * 256) * 4) =
            make_uint2(pack_bf16x2(v[u].x, v[u].y), pack_bf16x2(v[u].z, v[u].w));
    }
}

// ---------------------------------------------------------------------------
// Kernel 4 (mma.sync bf16 + 4-stage cp.async): out = gamma*(xb @ attn_b^T) + x
// CTA tile: M=256, N=128 pixels, 512 threads (16 warps 4Mx4N, warp 64x32).
// K-chunk 32, depth-4 pipeline, wait_group 2. Halves x L2 re-reads vs N=64.
// ---------------------------------------------------------------------------
#define KC       32
#define NKCHUNK  (NPX / KC)                 // 128
#define STG_A    (256 * 64)                 // 16 KB
#define STG_B    (128 * 64)                 // 8 KB
#define STG_SZ   (STG_A + STG_B)            // 24 KB
#define NSTG     4
#define OUT_SMEM (NSTG * STG_SZ)            // 96 KB

__global__ void __launch_bounds__(512, 1)
out_mma_kernel(const float* __restrict__ x,
               const __nv_bfloat16* __restrict__ xb,
               const __nv_bfloat16* __restrict__ attn_b,
               const float* __restrict__ gamma,
               float* __restrict__ outp)
{
    extern __shared__ __align__(128) uint8_t oStg[];

    const int b  = blockIdx.y;
    const int m0 = blockIdx.x * 128;
    const int tid = threadIdx.x;
    const int lane = tid & 31;
    const int wid = tid >> 5;               // 0..15
    const int warp_m = (wid & 3) * 64;      // 4 M groups of 64 rows
    const int warp_n = (wid >> 2) * 32;     // 4 N groups of 32 cols

    const float* A = x + (size_t)b * CCH * NPX;                  // fp32 (epilogue)
    const __nv_bfloat16* Ab = xb + (size_t)b * CCH * NPX;        // [256][4096]
    const __nv_bfloat16* Bb = attn_b + (size_t)b * NPX * NPX;    // [4096][4096]

    const uint32_t stg_u = smem_u32(oStg);

    // loaders: A 1024 x16B units (2/thread), B 512 units (1/thread)
    const int arow = tid >> 2;             // 0..127 (A rows arow, arow+128)
    const int aunit = tid & 3;

    float acc[4][4][4];
#pragma unroll
    for (int mi = 0; mi < 4; mi++)
#pragma unroll
        for (int ni = 0; ni < 4; ni++)
#pragma unroll
            for (int q = 0; q < 4; q++) acc[mi][ni][q] = 0.f;

    auto issue_chunk = [&](int kc, int s) {
        const uint32_t base = stg_u + (uint32_t)s * STG_SZ;
        const int k0 = kc * KC;
#pragma unroll
        for (int i = 0; i < 2; i++) {
            const int row = arow + i * 128;
            cp_async16(base + swz16(row, aunit),
                       Ab + (size_t)row * NPX + k0 + aunit * 8);
        }
        cp_async16(base + STG_A + swz16(arow, aunit),
                   Bb + (size_t)(m0 + arow) * NPX + k0 + aunit * 8);
        CP_COMMIT();
    };

    issue_chunk(0, 0);
    issue_chunk(1, 1);
    issue_chunk(2, 2);

    for (int kc = 0; kc < NKCHUNK; kc++) {
        const int s = kc & (NSTG - 1);
        CP_WAIT2();
        __syncthreads();
        if (kc + 3 < NKCHUNK) issue_chunk(kc + 3, (kc + 3) & (NSTG - 1));

        const uint32_t aBase = stg_u + (uint32_t)s * STG_SZ;
        const uint32_t bBase = aBase + STG_A;
#pragma unroll
        for (int kk = 0; kk < 2; kk++) {
            uint32_t afr[4][4];
#pragma unroll
            for (int mi = 0; mi < 4; mi++) {
                const int row = warp_m + mi * 16 + (lane & 7) + ((lane >> 3) & 1) * 8;
                const uint32_t chunk = (uint32_t)(kk * 2 + (lane >> 4));
                const uint32_t addr = aBase + (uint32_t)row * 64
                    + ((chunk ^ (((uint32_t)row >> 1) & 3u)) * 16);
                ldmatrix_x4(afr[mi][0], afr[mi][1], afr[mi][2], afr[mi][3], addr);
            }
            uint32_t bfr[4][2];
#pragma unroll
            for (int ng = 0; ng < 2; ng++) {
                const int row = warp_n + ng * 16 + (lane & 7) + ((lane >> 4) & 1) * 8;
                const uint32_t chunk = (uint32_t)(kk * 2 + ((lane >> 3) & 1));
                const uint32_t addr = bBase + (uint32_t)row * 64
                    + ((chunk ^ (((uint32_t)row >> 1) & 3u)) * 16);
                uint32_t r0, r1, r2, r3;
                ldmatrix_x4(r0, r1, r2, r3, addr);
                bfr[ng * 2 + 0][0] = r0; bfr[ng * 2 + 0][1] = r1;
                bfr[ng * 2 + 1][0] = r2; bfr[ng * 2 + 1][1] = r3;
            }
#pragma unroll
            for (int mi = 0; mi < 4; mi++)
#pragma unroll
                for (int ni = 0; ni < 4; ni++)
                    mma_16816(acc[mi][ni], afr[mi][0], afr[mi][1],
                              afr[mi][2], afr[mi][3],
                              bfr[ni][0], bfr[ni][1]);
        }
    }

    // ---- epilogue: out = gamma*acc + x (fp32 residual)
    const float g = gamma[0];
    float* ob = outp + (size_t)b * CCH * NPX;
#pragma unroll
    for (int mi = 0; mi < 4; mi++) {
        const int c0 = warp_m + mi * 16 + (lane >> 2);
#pragma unroll
        for (int ni = 0; ni < 4; ni++) {
            const int m = m0 + warp_n + ni * 8 + (lane & 3) * 2;
            {
                const float2 xv = *(const float2*)(A + (size_t)c0 * NPX + m);
                float2 v = make_float2(fmaf(g, acc[mi][ni][0], xv.x),
                                       fmaf(g, acc[mi][ni][1], xv.y));
                *(float2*)(ob + (size_t)c0 * NPX + m) = v;
            }
            {
                const int c1 = c0 + 8;
                const float2 xv = *(const float2*)(A + (size_t)c1 * NPX + m);
                float2 v = make_float2(fmaf(g, acc[mi][ni][2], xv.x),
                                       fmaf(g, acc[mi][ni][3], xv.y));
                *(float2*)(ob + (size_t)c1 * NPX + m) = v;
            }
        }
    }
}

// ---------------------------------------------------------------------------
// Launch: strip-interleaved energy->softmax (8 i-tiles = 16MB E, L2-hot).
// ---------------------------------------------------------------------------
extern "C" void kernel_launch(void* const* d_in, const int* in_sizes, int n_in,
                              void* d_out, int out_size)
{
    const float* x     = (const float*)d_in[0];
    const float* w_q   = (const float*)d_in[1];
    const float* b_q   = (const float*)d_in[2];
    const float* w_k   = (const float*)d_in[3];
    const float* b_k   = (const float*)d_in[4];
    const float* gamma = (const float*)d_in[5];

    float* outp = (float*)d_out;

    float* attn;
    if ((size_t)out_size >= OUT_ELEMS + ATTN_ELEMS) {
        attn = outp + OUT_ELEMS;
    } else {
        void* p = nullptr;
        cudaGetSymbolAddress(&p, g_attn_fb);
        attn = (float*)p;
    }

    void *pqh = nullptr, *pql = nullptr, *pkh = nullptr, *pkl = nullptr;
    void *pxb = nullptr, *pab = nullptr;
    cudaGetSymbolAddress(&pqh, g_Qh);
    cudaGetSymbolAddress(&pql, g_Ql);
    cudaGetSymbolAddress(&pkh, g_Kh);
    cudaGetSymbolAddress(&pkl, g_Kl);
    cudaGetSymbolAddress(&pxb, g_Xb);
    cudaGetSymbolAddress(&pab, g_attn_b);

    static int smem_set = 0;
    if (!smem_set) {
        cudaFuncSetAttribute(energy_mma_kernel,
                             cudaFuncAttributeMaxDynamicSharedMemorySize, E_SMEM);
        cudaFuncSetAttribute(out_mma_kernel,
                             cudaFuncAttributeMaxDynamicSharedMemorySize, OUT_SMEM);
        smem_set = 1;
    }

    dim3 gp(NPX / 64, BB);
    proj2_kernel<<<gp, 256>>>(x, w_q, b_q, w_k, b_k,
                              (__nv_bfloat16*)pqh, (__nv_bfloat16*)pql,
                              (__nv_bfloat16*)pkh, (__nv_bfloat16*)pkl);

    xconv_kernel<<<2048, 256>>>(x, (__nv_bfloat16*)pxb);

    // strips of 8 i-tiles (1024 rows, 16 MB of E -> stays L2-hot for softmax)
    dim3 ge(NPX / 128, 8);
    for (int b = 0; b < BB; b++) {
        for (int is = 0; is < 4; is++) {
            energy_mma_kernel<<<ge, 256, E_SMEM>>>(attn, b, is * 8);
            const size_t rofs = (size_t)b * NPX * NPX + (size_t)is * 1024 * NPX;
            softmax_kernel<<<1024, 256>>>(attn + rofs,
                                          (__nv_bfloat16*)pab + rofs);
        }
    }

    dim3 go(NPX / 128, BB);
    out_mma_kernel<<<go, 512, OUT_SMEM>>>(x, (const __nv_bfloat16*)pxb,
                                          (const __nv_bfloat16*)pab, gamma, outp);
}

// round 15
// speedup vs baseline: 1.1547x; 1.1547x over previous
#include <cuda_runtime.h>
#include <cuda_bf16.h>
#include <cstdint>

// Problem constants
#define BB   4
#define CCH  256
#define NPX  4096     // W*H = 64*64
#define CQ   64       // C/4

#define OUT_ELEMS  ((size_t)BB * CCH * NPX)          // 4,194,304
#define ATTN_ELEMS ((size_t)BB * NPX * NPX)          // 67,108,864

// Scratch: pre-split bf16 Q/K stored [b][n][cq]; bf16 x [b][c][n]; bf16 attn
__device__ __nv_bfloat16 g_Qh[BB * NPX * CQ];
__device__ __nv_bfloat16 g_Ql[BB * NPX * CQ];
__device__ __nv_bfloat16 g_Kh[BB * NPX * CQ];
__device__ __nv_bfloat16 g_Kl[BB * NPX * CQ];
__device__ __nv_bfloat16 g_Xb[BB * CCH * NPX];
__device__ __nv_bfloat16 g_attn_b[ATTN_ELEMS];
// Fallback attention buffer in case d_out only holds `out`
__device__ float g_attn_fb[ATTN_ELEMS];

// ===========================================================================
// Helpers (base sm_100-legal: ldmatrix + mma.sync + cp.async)
// ===========================================================================
__device__ __forceinline__ uint32_t smem_u32(const void* p) {
    uint32_t a;
    asm("{ .reg .u64 t; cvta.to.shared.u64 t, %1; cvt.u32.u64 %0, t; }"
        : "=r"(a) : "l"(p));
    return a;
}
// Pack two f32 into bf16x2 {lo, hi}. Single SASS op.
__device__ __forceinline__ uint32_t pack_bf16x2(float lo, float hi) {
    uint32_t r;
    asm("cvt.rn.bf16x2.f32 %0, %1, %2;" : "=r"(r) : "f"(hi), "f"(lo));
    return r;
}
__device__ __forceinline__ void ldmatrix_x4(uint32_t& r0, uint32_t& r1,
                                            uint32_t& r2, uint32_t& r3,
                                            uint32_t addr) {
    asm volatile("ldmatrix.sync.aligned.m8n8.x4.shared.b16 {%0,%1,%2,%3}, [%4];"
                 : "=r"(r0), "=r"(r1), "=r"(r2), "=r"(r3) : "r"(addr));
}
__device__ __forceinline__ void mma_16816(float* c, uint32_t a0, uint32_t a1,
                                          uint32_t a2, uint32_t a3,
                                          uint32_t b0, uint32_t b1) {
    asm volatile(
        "mma.sync.aligned.m16n8k16.row.col.f32.bf16.bf16.f32 "
        "{%0,%1,%2,%3}, {%4,%5,%6,%7}, {%8,%9}, {%0,%1,%2,%3};"
        : "+f"(c[0]), "+f"(c[1]), "+f"(c[2]), "+f"(c[3])
        : "r"(a0), "r"(a1), "r"(a2), "r"(a3), "r"(b0), "r"(b1));
}
__device__ __forceinline__ void cp_async16(uint32_t smem_addr, const void* gptr) {
    asm volatile("cp.async.cg.shared.global [%0], [%1], 16;"
                 :: "r"(smem_addr), "l"(gptr));
}
#define CP_COMMIT() asm volatile("cp.async.commit_group;")
#define CP_WAIT0()  asm volatile("cp.async.wait_group 0;")
#define CP_WAIT1()  asm volatile("cp.async.wait_group 1;")
#define CP_WAIT3()  asm volatile("cp.async.wait_group 3;")

// 64B-pitch swizzle (16B units 0..3)
__device__ __forceinline__ uint32_t swz16(int row, int unit) {
    return (uint32_t)row * 64 + (((uint32_t)unit ^ (((uint32_t)row >> 1) & 3u)) * 16);
}
// 128B-pitch swizzle (16B units 0..7)
__device__ __forceinline__ uint32_t swz128(int row, int unit) {
    return (uint32_t)row * 128 + (((uint32_t)unit ^ ((uint32_t)row & 7u)) * 16);
}

// ---------------------------------------------------------------------------
// Kernel 0: x -> bf16 copy
// ---------------------------------------------------------------------------
__global__ void xconv_kernel(const float* __restrict__ x, __nv_bfloat16* __restrict__ xb)
{
    const size_t n4 = OUT_ELEMS / 4;
    for (size_t i = (size_t)blockIdx.x * blockDim.x + threadIdx.x; i < n4;
         i += (size_t)gridDim.x * blockDim.x) {
        float4 v = *(const float4*)(x + i * 4);
        *(uint2*)(xb + i * 4) = make_uint2(pack_bf16x2(v.x, v.y),
                                           pack_bf16x2(v.z, v.w));
    }
}

// ---------------------------------------------------------------------------
// Kernel 1: fused Q+K projection + hi/lo split (shared x tile).
// ---------------------------------------------------------------------------
__global__ void proj2_kernel(const float* __restrict__ x,
                             const float* __restrict__ wq,
                             const float* __restrict__ bq,
                             const float* __restrict__ wk,
                             const float* __restrict__ bk,
                             __nv_bfloat16* __restrict__ qH,
                             __nv_bfloat16* __restrict__ qL,
                             __nv_bfloat16* __restrict__ kH,
                             __nv_bfloat16* __restrict__ kL)
{
    const int b  = blockIdx.y;
    const int n0 = blockIdx.x * 64;
    const int tid = threadIdx.x;
    const int tx = tid & 15;        // n dimension
    const int ty = tid >> 4;        // oc dimension

    __shared__ __align__(16) float Xs[32][64];    // [c][n]
    __shared__ __align__(16) float Wq[32][68];    // [c][oc]
    __shared__ __align__(16) float Wk[32][68];    // [c][oc]

    const float* xb = x + (size_t)b * CCH * NPX;

    float aq[4][4], ak[4][4];
#pragma unroll
    for (int i = 0; i < 4; i++)
#pragma unroll
        for (int j = 0; j < 4; j++) { aq[i][j] = 0.f; ak[i][j] = 0.f; }

    for (int c0 = 0; c0 < CCH; c0 += 32) {
#pragma unroll
        for (int r = 0; r < 2; r++) {
            int idx = tid + r * 256;
            int cc  = idx >> 4;
            int nq  = (idx & 15) << 2;
            float4 v = *(const float4*)(xb + (size_t)(c0 + cc) * NPX + n0 + nq);
            *(float4*)(&Xs[cc][nq]) = v;
        }
#pragma unroll
        for (int r = 0; r < 2; r++) {
            int idx = tid + r * 256;
            int oc  = idx >> 3;
            int cq  = (idx & 7) << 2;
            float4 v = *(const float4*)(wq + oc * CCH + c0 + cq);
            Wq[cq + 0][oc] = v.x; Wq[cq + 1][oc] = v.y;
            Wq[cq + 2][oc] = v.z; Wq[cq + 3][oc] = v.w;
            float4 u = *(const float4*)(wk + oc * CCH + c0 + cq);
            Wk[cq + 0][oc] = u.x; Wk[cq + 1][oc] = u.y;
            Wk[cq + 2][oc] = u.z; Wk[cq + 3][oc] = u.w;
        }
        __syncthreads();
#pragma unroll
        for (int cc = 0; cc < 32; cc++) {
            float4 q4 = *(const float4*)(&Wq[cc][ty * 4]);
            float4 k4 = *(const float4*)(&Wk[cc][ty * 4]);
            float4 bv = *(const float4*)(&Xs[cc][tx * 4]);
            float qv[4] = {q4.x, q4.y, q4.z, q4.w};
            float kv[4] = {k4.x, k4.y, k4.z, k4.w};
            float bw[4] = {bv.x, bv.y, bv.z, bv.w};
#pragma unroll
            for (int i = 0; i < 4; i++)
#pragma unroll
                for (int j = 0; j < 4; j++) {
                    aq[i][j] = fmaf(qv[i], bw[j], aq[i][j]);
                    ak[i][j] = fmaf(kv[i], bw[j], ak[i][j]);
                }
        }
        __syncthreads();
    }

    float4 bqv = *(const float4*)(bq + ty * 4);
    float4 bkv = *(const float4*)(bk + ty * 4);
    float bq4[4] = {bqv.x, bqv.y, bqv.z, bqv.w};
    float bk4[4] = {bkv.x, bkv.y, bkv.z, bkv.w};
    const size_t ob = (size_t)b * NPX * CQ;
#pragma unroll
    for (int j = 0; j < 4; j++) {
        const int n = n0 + tx * 4 + j;
        const size_t ofs = ob + (size_t)n * CQ + ty * 4;
        {
            float v0 = aq[0][j] + bq4[0], v1 = aq[1][j] + bq4[1];
            float v2 = aq[2][j] + bq4[2], v3 = aq[3][j] + bq4[3];
            float h0 = __bfloat162float(__float2bfloat16(v0));
            float h1 = __bfloat162float(__float2bfloat16(v1));
            float h2 = __bfloat162float(__float2bfloat16(v2));
            float h3 = __bfloat162float(__float2bfloat16(v3));
            *(uint2*)(qH + ofs) = make_uint2(pack_bf16x2(h0, h1), pack_bf16x2(h2, h3));
            *(uint2*)(qL + ofs) = make_uint2(pack_bf16x2(v0 - h0, v1 - h1),
                                             pack_bf16x2(v2 - h2, v3 - h3));
        }
        {
            float v0 = ak[0][j] + bk4[0], v1 = ak[1][j] + bk4[1];
            float v2 = ak[2][j] + bk4[2], v3 = ak[3][j] + bk4[3];
            float h0 = __bfloat162float(__float2bfloat16(v0));
            float h1 = __bfloat162float(__float2bfloat16(v1));
            float h2 = __bfloat162float(__float2bfloat16(v2));
            float h3 = __bfloat162float(__float2bfloat16(v3));
            *(uint2*)(kH + ofs) = make_uint2(pack_bf16x2(h0, h1), pack_bf16x2(h2, h3));
            *(uint2*)(kL + ofs) = make_uint2(pack_bf16x2(v0 - h0, v1 - h1),
                                             pack_bf16x2(v2 - h2, v3 - h3));
        }
    }
}

// ---------------------------------------------------------------------------
// Kernel 2 (tensor cores, pre-split bf16): E[i][j] = qh*kh + qh*kl + ql*kh
// CTA tile 128x128, FULL K=64 resident in 64KB dynamic smem (128B pitch).
// Single batch per launch (L2 interleave with softmax). [round-13 proven]
// ---------------------------------------------------------------------------
#define E_MAT   (128 * 128)          // 16 KB per matrix
#define E_SMEM  (4 * E_MAT)          // 64 KB

__global__ void __launch_bounds__(256, 2) energy_mma_kernel(float* __restrict__ E,
                                                            int b)
{
    extern __shared__ __align__(128) uint8_t es[];

    const int i0 = blockIdx.y * 128;
    const int j0 = blockIdx.x * 128;
    const int tid = threadIdx.x;
    const int lane = tid & 31;
    const int wid = tid >> 5;
    const int warp_m = (wid & 1) * 64;      // 2 M groups of 64
    const int warp_n = (wid >> 1) * 32;     // 4 N groups of 32

    const __nv_bfloat16* Qh = g_Qh + (size_t)b * NPX * CQ;
    const __nv_bfloat16* Ql = g_Ql + (size_t)b * NPX * CQ;
    const __nv_bfloat16* Kh = g_Kh + (size_t)b * NPX * CQ;
    const __nv_bfloat16* Kl = g_Kl + (size_t)b * NPX * CQ;

    const uint32_t qh_u = smem_u32(es);
    const uint32_t ql_u = qh_u + E_MAT;
    const uint32_t kh_u = qh_u + 2 * E_MAT;
    const uint32_t kl_u = qh_u + 3 * E_MAT;

#pragma unroll
    for (int c = 0; c < 2; c++) {
#pragma unroll
        for (int i = 0; i < 2; i++) {
            const int idx = tid + i * 256;            // 0..511
            const int row = idx >> 2;                 // 0..127
            const int u   = (idx & 3) + c * 4;        // 16B unit 0..7
            const uint32_t off = swz128(row, u);
            const size_t qo = (size_t)(i0 + row) * CQ + u * 8;
            const size_t ko = (size_t)(j0 + row) * CQ + u * 8;
            cp_async16(qh_u + off, Qh + qo);
            cp_async16(ql_u + off, Ql + qo);
            cp_async16(kh_u + off, Kh + ko);
            cp_async16(kl_u + off, Kl + ko);
        }
        CP_COMMIT();
    }

    float acc[4][4][4];
#pragma unroll
    for (int mi = 0; mi < 4; mi++)
#pragma unroll
        for (int ni = 0; ni < 4; ni++)
#pragma unroll
            for (int q = 0; q < 4; q++) acc[mi][ni][q] = 0.f;

    CP_WAIT1();
    __syncthreads();

#pragma unroll
    for (int ks = 0; ks < 4; ks++) {
        if (ks == 2) {
            CP_WAIT0();
            __syncthreads();
        }
        uint32_t ah[4][4];
#pragma unroll
        for (int mi = 0; mi < 4; mi++) {
            const int row = warp_m + mi * 16 + (lane & 7) + ((lane >> 3) & 1) * 8;
            const int u = ks * 2 + (lane >> 4);
            ldmatrix_x4(ah[mi][0], ah[mi][1], ah[mi][2], ah[mi][3],
                        qh_u + swz128(row, u));
        }
        uint32_t bh[4][2], bl[4][2];
#pragma unroll
        for (int ng = 0; ng < 2; ng++) {
            const int row = warp_n + ng * 16 + (lane & 7) + ((lane >> 4) & 1) * 8;
            const int u = ks * 2 + ((lane >> 3) & 1);
            uint32_t r0, r1, r2, r3;
            ldmatrix_x4(r0, r1, r2, r3, kh_u + swz128(row, u));
            bh[ng * 2 + 0][0] = r0; bh[ng * 2 + 0][1] = r1;
            bh[ng * 2 + 1][0] = r2; bh[ng * 2 + 1][1] = r3;
            ldmatrix_x4(r0, r1, r2, r3, kl_u + swz128(row, u));
            bl[ng * 2 + 0][0] = r0; bl[ng * 2 + 0][1] = r1;
            bl[ng * 2 + 1][0] = r2; bl[ng * 2 + 1][1] = r3;
        }
#pragma unroll
        for (int mi = 0; mi < 4; mi++)
#pragma unroll
            for (int ni = 0; ni < 4; ni++) {
                mma_16816(acc[mi][ni], ah[mi][0], ah[mi][1], ah[mi][2], ah[mi][3],
                          bh[ni][0], bh[ni][1]);
                mma_16816(acc[mi][ni], ah[mi][0], ah[mi][1], ah[mi][2], ah[mi][3],
                          bl[ni][0], bl[ni][1]);
            }
        uint32_t al[4][4];
#pragma unroll
        for (int mi = 0; mi < 4; mi++) {
            const int row = warp_m + mi * 16 + (lane & 7) + ((lane >> 3) & 1) * 8;
            const int u = ks * 2 + (lane >> 4);
            ldmatrix_x4(al[mi][0], al[mi][1], al[mi][2], al[mi][3],
                        ql_u + swz128(row, u));
        }
#pragma unroll
        for (int mi = 0; mi < 4; mi++)
#pragma unroll
            for (int ni = 0; ni < 4; ni++)
                mma_16816(acc[mi][ni], al[mi][0], al[mi][1], al[mi][2], al[mi][3],
                          bh[ni][0], bh[ni][1]);
    }

    float* Eb = E + (size_t)b * NPX * NPX;
#pragma unroll
    for (int mi = 0; mi < 4; mi++) {
        const int r0 = i0 + warp_m + mi * 16 + (lane >> 2);
#pragma unroll
        for (int ni = 0; ni < 4; ni++) {
            const int j = j0 + warp_n + ni * 8 + (lane & 3) * 2;
            *(float2*)(Eb + (size_t)r0 * NPX + j) =
                make_float2(acc[mi][ni][0], acc[mi][ni][1]);
            *(float2*)(Eb + (size_t)(r0 + 8) * NPX + j) =
                make_float2(acc[mi][ni][2], acc[mi][ni][3]);
        }
    }
}

// ---------------------------------------------------------------------------
// Kernel 3: row softmax in place + bf16 copy. One block per row; per-batch
// pointers so E reads hit L2 right after energy(b). [round-13 proven]
// ---------------------------------------------------------------------------
__global__ void softmax_kernel(float* __restrict__ attn,
                               __nv_bfloat16* __restrict__ attn_b)
{
    __shared__ float red[8];
    const size_t row = blockIdx.x;
    float* r = attn + row * NPX;
    __nv_bfloat16* rb = attn_b + row * NPX;
    const int t = threadIdx.x;
    const int lane = t & 31;
    const int warp = t >> 5;

    float4 v[4];
#pragma unroll
    for (int u = 0; u < 4; u++)
        v[u] = *(const float4*)(r + (size_t)(t + u * 256) * 4);

    float mx = -3.402823e38f;
#pragma unroll
    for (int u = 0; u < 4; u++)
        mx = fmaxf(mx, fmaxf(fmaxf(v[u].x, v[u].y), fmaxf(v[u].z, v[u].w)));
#pragma unroll
    for (int o = 16; o > 0; o >>= 1)
        mx = fmaxf(mx, __shfl_xor_sync(0xFFFFFFFFu, mx, o));
    if (lane == 0) red[warp] = mx;
    __syncthreads();
    float rowmax = red[0];
#pragma unroll
    for (int u = 1; u < 8; u++) rowmax = fmaxf(rowmax, red[u]);
    __syncthreads();

    float s = 0.f;
#pragma unroll
    for (int u = 0; u < 4; u++) {
        v[u].x = __expf(v[u].x - rowmax);
        v[u].y = __expf(v[u].y - rowmax);
        v[u].z = __expf(v[u].z - rowmax);
        v[u].w = __expf(v[u].w - rowmax);
        s += v[u].x + v[u].y + v[u].z + v[u].w;
    }
#pragma unroll
    for (int o = 16; o > 0; o >>= 1)
        s += __shfl_xor_sync(0xFFFFFFFFu, s, o);
    if (lane == 0) red[warp] = s;
    __syncthreads();
    float total = 0.f;
#pragma unroll
    for (int u = 0; u < 8; u++) total += red[u];
    float inv = 1.0f / total;

#pragma unroll
    for (int u = 0; u < 4; u++) {
        v[u].x *= inv; v[u].y *= inv; v[u].z *= inv; v[u].w *= inv;
        *(float4*)(r + (size_t)(t + u * 256) * 4) = v[u];
        *(uint2*)(rb + (size_t)(t + u * 256) * 4) =
            make_uint2(pack_bf16x2(v[u].x, v[u].y), pack_bf16x2(v[u].z, v[u].w));
    }
}

// ---------------------------------------------------------------------------
// Kernel 4 (mma.sync bf16 + 5-stage cp.async): out = gamma*(xb @ attn_b^T) + x
// CTA tile: M=256, N=64 pixels, K-chunk 32. Depth-5 pipeline, prefetch-4,
// wait_group 3. 100KB smem, 2 CTAs/SM.
// ---------------------------------------------------------------------------
#define KC       32
#define NKCHUNK  (NPX / KC)                 // 128
#define STG_A    (256 * 64)                 // 16 KB
#define STG_B    (64 * 64)                  // 4 KB
#define STG_SZ   (STG_A + STG_B)            // 20 KB
#define NSTG     5
#define OUT_SMEM (NSTG * STG_SZ)            // 100 KB

__global__ void __launch_bounds__(256, 2)
out_mma_kernel(const float* __restrict__ x,
               const __nv_bfloat16* __restrict__ xb,
               const __nv_bfloat16* __restrict__ attn_b,
               const float* __restrict__ gamma,
               float* __restrict__ outp)
{
    extern __shared__ __align__(128) uint8_t oStg[];

    const int b  = blockIdx.y;
    const int m0 = blockIdx.x * 64;
    const int tid = threadIdx.x;
    const int lane = tid & 31;
    const int wid = tid >> 5;
    const int warp_m = (wid & 3) * 64;      // 4 M groups of 64 rows
    const int warp_n = (wid >> 2) * 32;     // 2 N groups of 32 cols

    const float* A = x + (size_t)b * CCH * NPX;                  // fp32 (epilogue)
    const __nv_bfloat16* Ab = xb + (size_t)b * CCH * NPX;        // [256][4096]
    const __nv_bfloat16* Bb = attn_b + (size_t)b * NPX * NPX;    // [4096][4096]

    const uint32_t stg_u = smem_u32(oStg);

    const int arow = tid >> 2;             // base row 0..63 (A rows arow + i*64)
    const int aunit = tid & 3;

    float acc[4][4][4];
#pragma unroll
    for (int mi = 0; mi < 4; mi++)
#pragma unroll
        for (int ni = 0; ni < 4; ni++)
#pragma unroll
            for (int q = 0; q < 4; q++) acc[mi][ni][q] = 0.f;

    auto issue_chunk = [&](int kc, int s) {
        const uint32_t base = stg_u + (uint32_t)s * STG_SZ;
        const int k0 = kc * KC;
#pragma unroll
        for (int i = 0; i < 4; i++) {
            const int row = arow + i * 64;
            cp_async16(base + swz16(row, aunit),
                       Ab + (size_t)row * NPX + k0 + aunit * 8);
        }
        cp_async16(base + STG_A + swz16(arow, aunit),
                   Bb + (size_t)(m0 + arow) * NPX + k0 + aunit * 8);
        CP_COMMIT();
    };

    issue_chunk(0, 0);
    issue_chunk(1, 1);
    issue_chunk(2, 2);
    issue_chunk(3, 3);

    int s = 0;
    for (int kc = 0; kc < NKCHUNK; kc++) {
        CP_WAIT3();
        __syncthreads();
        if (kc + 4 < NKCHUNK) {
            int sn = s + 4; if (sn >= NSTG) sn -= NSTG;
            issue_chunk(kc + 4, sn);
        }

        const uint32_t aBase = stg_u + (uint32_t)s * STG_SZ;
        const uint32_t bBase = aBase + STG_A;
#pragma unroll
        for (int kk = 0; kk < 2; kk++) {
            uint32_t afr[4][4];
#pragma unroll
            for (int mi = 0; mi < 4; mi++) {
                const int row = warp_m + mi * 16 + (lane & 7) + ((lane >> 3) & 1) * 8;
                const uint32_t chunk = (uint32_t)(kk * 2 + (lane >> 4));
                const uint32_t addr = aBase + (uint32_t)row * 64
                    + ((chunk ^ (((uint32_t)row >> 1) & 3u)) * 16);
                ldmatrix_x4(afr[mi][0], afr[mi][1], afr[mi][2], afr[mi][3], addr);
            }
            uint32_t bfr[4][2];
#pragma unroll
            for (int ng = 0; ng < 2; ng++) {
                const int row = warp_n + ng * 16 + (lane & 7) + ((lane >> 4) & 1) * 8;
                const uint32_t chunk = (uint32_t)(kk * 2 + ((lane >> 3) & 1));
                const uint32_t addr = bBase + (uint32_t)row * 64
                    + ((chunk ^ (((uint32_t)row >> 1) & 3u)) * 16);
                uint32_t r0, r1, r2, r3;
                ldmatrix_x4(r0, r1, r2, r3, addr);
                bfr[ng * 2 + 0][0] = r0; bfr[ng * 2 + 0][1] = r1;
                bfr[ng * 2 + 1][0] = r2; bfr[ng * 2 + 1][1] = r3;
            }
#pragma unroll
            for (int mi = 0; mi < 4; mi++)
#pragma unroll
                for (int ni = 0; ni < 4; ni++)
                    mma_16816(acc[mi][ni], afr[mi][0], afr[mi][1],
                              afr[mi][2], afr[mi][3],
                              bfr[ni][0], bfr[ni][1]);
        }
        if (++s == NSTG) s = 0;
    }

    // ---- epilogue: out = gamma*acc + x (fp32 residual)
    const float g = gamma[0];
    float* ob = outp + (size_t)b * CCH * NPX;
#pragma unroll
    for (int mi = 0; mi < 4; mi++) {
        const int c0 = warp_m + mi * 16 + (lane >> 2);
#pragma unroll
        for (int ni = 0; ni < 4; ni++) {
            const int m = m0 + warp_n + ni * 8 + (lane & 3) * 2;
            {
                const float2 xv = *(const float2*)(A + (size_t)c0 * NPX + m);
                float2 v = make_float2(fmaf(g, acc[mi][ni][0], xv.x),
                                       fmaf(g, acc[mi][ni][1], xv.y));
                *(float2*)(ob + (size_t)c0 * NPX + m) = v;
            }
            {
                const int c1 = c0 + 8;
                const float2 xv = *(const float2*)(A + (size_t)c1 * NPX + m);
                float2 v = make_float2(fmaf(g, acc[mi][ni][2], xv.x),
                                       fmaf(g, acc[mi][ni][3], xv.y));
                *(float2*)(ob + (size_t)c1 * NPX + m) = v;
            }
        }
    }
}

// ---------------------------------------------------------------------------
// Launch: per-batch energy->softmax interleave (round-13 proven structure).
// ---------------------------------------------------------------------------
extern "C" void kernel_launch(void* const* d_in, const int* in_sizes, int n_in,
                              void* d_out, int out_size)
{
    const float* x     = (const float*)d_in[0];
    const float* w_q   = (const float*)d_in[1];
    const float* b_q   = (const float*)d_in[2];
    const float* w_k   = (const float*)d_in[3];
    const float* b_k   = (const float*)d_in[4];
    const float* gamma = (const float*)d_in[5];

    float* outp = (float*)d_out;

    float* attn;
    if ((size_t)out_size >= OUT_ELEMS + ATTN_ELEMS) {
        attn = outp + OUT_ELEMS;
    } else {
        void* p = nullptr;
        cudaGetSymbolAddress(&p, g_attn_fb);
        attn = (float*)p;
    }

    void *pqh = nullptr, *pql = nullptr, *pkh = nullptr, *pkl = nullptr;
    void *pxb = nullptr, *pab = nullptr;
    cudaGetSymbolAddress(&pqh, g_Qh);
    cudaGetSymbolAddress(&pql, g_Ql);
    cudaGetSymbolAddress(&pkh, g_Kh);
    cudaGetSymbolAddress(&pkl, g_Kl);
    cudaGetSymbolAddress(&pxb, g_Xb);
    cudaGetSymbolAddress(&pab, g_attn_b);

    static int smem_set = 0;
    if (!smem_set) {
        cudaFuncSetAttribute(energy_mma_kernel,
                             cudaFuncAttributeMaxDynamicSharedMemorySize, E_SMEM);
        cudaFuncSetAttribute(out_mma_kernel,
                             cudaFuncAttributeMaxDynamicSharedMemorySize, OUT_SMEM);
        smem_set = 1;
    }

    dim3 gp(NPX / 64, BB);
    proj2_kernel<<<gp, 256>>>(x, w_q, b_q, w_k, b_k,
                              (__nv_bfloat16*)pqh, (__nv_bfloat16*)pql,
                              (__nv_bfloat16*)pkh, (__nv_bfloat16*)pkl);

    xconv_kernel<<<2048, 256>>>(x, (__nv_bfloat16*)pxb);

    dim3 ge(NPX / 128, NPX / 128);
    for (int b = 0; b < BB; b++) {
        energy_mma_kernel<<<ge, 256, E_SMEM>>>(attn, b);
        softmax_kernel<<<NPX, 256>>>(attn + (size_t)b * NPX * NPX,
                                     (__nv_bfloat16*)pab + (size_t)b * NPX * NPX);
    }

    dim3 go(NPX / 64, BB);
    out_mma_kernel<<<go, 256, OUT_SMEM>>>(x, (const __nv_bfloat16*)pxb,
                                          (const __nv_bfloat16*)pab, gamma, outp);
}

// round 16
// speedup vs baseline: 1.1555x; 1.0008x over previous
#include <cuda_runtime.h>
#include <cuda_bf16.h>
#include <cstdint>

// Problem constants
#define BB   4
#define CCH  256
#define NPX  4096     // W*H = 64*64
#define CQ   64       // C/4

#define OUT_ELEMS  ((size_t)BB * CCH * NPX)          // 4,194,304
#define ATTN_ELEMS ((size_t)BB * NPX * NPX)          // 67,108,864

// Scratch: pre-split bf16 Q/K stored [b][n][cq]; bf16 x [b][c][n]; bf16 attn
__device__ __nv_bfloat16 g_Qh[BB * NPX * CQ];
__device__ __nv_bfloat16 g_Ql[BB * NPX * CQ];
__device__ __nv_bfloat16 g_Kh[BB * NPX * CQ];
__device__ __nv_bfloat16 g_Kl[BB * NPX * CQ];
__device__ __nv_bfloat16 g_Xb[BB * CCH * NPX];
__device__ __nv_bfloat16 g_attn_b[ATTN_ELEMS];
// Fallback attention buffer in case d_out only holds `out`
__device__ float g_attn_fb[ATTN_ELEMS];

// ===========================================================================
// Helpers (base sm_100-legal: ldmatrix + mma.sync + cp.async)
// ===========================================================================
__device__ __forceinline__ uint32_t smem_u32(const void* p) {
    uint32_t a;
    asm("{ .reg .u64 t; cvta.to.shared.u64 t, %1; cvt.u32.u64 %0, t; }"
        : "=r"(a) : "l"(p));
    return a;
}
// Pack two f32 into bf16x2 {lo, hi}. Single SASS op.
__device__ __forceinline__ uint32_t pack_bf16x2(float lo, float hi) {
    uint32_t r;
    asm("cvt.rn.bf16x2.f32 %0, %1, %2;" : "=r"(r) : "f"(hi), "f"(lo));
    return r;
}
__device__ __forceinline__ void ldmatrix_x4(uint32_t& r0, uint32_t& r1,
                                            uint32_t& r2, uint32_t& r3,
                                            uint32_t addr) {
    asm volatile("ldmatrix.sync.aligned.m8n8.x4.shared.b16 {%0,%1,%2,%3}, [%4];"
                 : "=r"(r0), "=r"(r1), "=r"(r2), "=r"(r3) : "r"(addr));
}
__device__ __forceinline__ void mma_16816(float* c, uint32_t a0, uint32_t a1,
                                          uint32_t a2, uint32_t a3,
                                          uint32_t b0, uint32_t b1) {
    asm volatile(
        "mma.sync.aligned.m16n8k16.row.col.f32.bf16.bf16.f32 "
        "{%0,%1,%2,%3}, {%4,%5,%6,%7}, {%8,%9}, {%0,%1,%2,%3};"
        : "+f"(c[0]), "+f"(c[1]), "+f"(c[2]), "+f"(c[3])
        : "r"(a0), "r"(a1), "r"(a2), "r"(a3), "r"(b0), "r"(b1));
}
__device__ __forceinline__ void cp_async16(uint32_t smem_addr, const void* gptr) {
    asm volatile("cp.async.cg.shared.global [%0], [%1], 16;"
                 :: "r"(smem_addr), "l"(gptr));
}
#define CP_COMMIT() asm volatile("cp.async.commit_group;")
#define CP_WAIT0()  asm volatile("cp.async.wait_group 0;")
#define CP_WAIT1()  asm volatile("cp.async.wait_group 1;")
#define CP_WAIT2()  asm volatile("cp.async.wait_group 2;")

// 64B-pitch swizzle (16B units 0..3)
__device__ __forceinline__ uint32_t swz16(int row, int unit) {
    return (uint32_t)row * 64 + (((uint32_t)unit ^ (((uint32_t)row >> 1) & 3u)) * 16);
}
// 128B-pitch swizzle (16B units 0..7)
__device__ __forceinline__ uint32_t swz128(int row, int unit) {
    return (uint32_t)row * 128 + (((uint32_t)unit ^ ((uint32_t)row & 7u)) * 16);
}

// ---------------------------------------------------------------------------
// Kernel 0: x -> bf16 copy
// ---------------------------------------------------------------------------
__global__ void xconv_kernel(const float* __restrict__ x, __nv_bfloat16* __restrict__ xb)
{
    const size_t n4 = OUT_ELEMS / 4;
    for (size_t i = (size_t)blockIdx.x * blockDim.x + threadIdx.x; i < n4;
         i += (size_t)gridDim.x * blockDim.x) {
        float4 v = *(const float4*)(x + i * 4);
        *(uint2*)(xb + i * 4) = make_uint2(pack_bf16x2(v.x, v.y),
                                           pack_bf16x2(v.z, v.w));
    }
}

// ---------------------------------------------------------------------------
// Kernel 1: fused Q+K projection + hi/lo split (shared x tile).
// ---------------------------------------------------------------------------
__global__ void proj2_kernel(const float* __restrict__ x,
                             const float* __restrict__ wq,
                             const float* __restrict__ bq,
                             const float* __restrict__ wk,
                             const float* __restrict__ bk,
                             __nv_bfloat16* __restrict__ qH,
                             __nv_bfloat16* __restrict__ qL,
                             __nv_bfloat16* __restrict__ kH,
                             __nv_bfloat16* __restrict__ kL)
{
    const int b  = blockIdx.y;
    const int n0 = blockIdx.x * 64;
    const int tid = threadIdx.x;
    const int tx = tid & 15;        // n dimension
    const int ty = tid >> 4;        // oc dimension

    __shared__ __align__(16) float Xs[32][64];    // [c][n]
    __shared__ __align__(16) float Wq[32][68];    // [c][oc]
    __shared__ __align__(16) float Wk[32][68];    // [c][oc]

    const float* xb = x + (size_t)b * CCH * NPX;

    float aq[4][4], ak[4][4];
#pragma unroll
    for (int i = 0; i < 4; i++)
#pragma unroll
        for (int j = 0; j < 4; j++) { aq[i][j] = 0.f; ak[i][j] = 0.f; }

    for (int c0 = 0; c0 < CCH; c0 += 32) {
#pragma unroll
        for (int r = 0; r < 2; r++) {
            int idx = tid + r * 256;
            int cc  = idx >> 4;
            int nq  = (idx & 15) << 2;
            float4 v = *(const float4*)(xb + (size_t)(c0 + cc) * NPX + n0 + nq);
            *(float4*)(&Xs[cc][nq]) = v;
        }
#pragma unroll
        for (int r = 0; r < 2; r++) {
            int idx = tid + r * 256;
            int oc  = idx >> 3;
            int cq  = (idx & 7) << 2;
            float4 v = *(const float4*)(wq + oc * CCH + c0 + cq);
            Wq[cq + 0][oc] = v.x; Wq[cq + 1][oc] = v.y;
            Wq[cq + 2][oc] = v.z; Wq[cq + 3][oc] = v.w;
            float4 u = *(const float4*)(wk + oc * CCH + c0 + cq);
            Wk[cq + 0][oc] = u.x; Wk[cq + 1][oc] = u.y;
            Wk[cq + 2][oc] = u.z; Wk[cq + 3][oc] = u.w;
        }
        __syncthreads();
#pragma unroll
        for (int cc = 0; cc < 32; cc++) {
            float4 q4 = *(const float4*)(&Wq[cc][ty * 4]);
            float4 k4 = *(const float4*)(&Wk[cc][ty * 4]);
            float4 bv = *(const float4*)(&Xs[cc][tx * 4]);
            float qv[4] = {q4.x, q4.y, q4.z, q4.w};
            float kv[4] = {k4.x, k4.y, k4.z, k4.w};
            float bw[4] = {bv.x, bv.y, bv.z, bv.w};
#pragma unroll
            for (int i = 0; i < 4; i++)
#pragma unroll
                for (int j = 0; j < 4; j++) {
                    aq[i][j] = fmaf(qv[i], bw[j], aq[i][j]);
                    ak[i][j] = fmaf(kv[i], bw[j], ak[i][j]);
                }
        }
        __syncthreads();
    }

    float4 bqv = *(const float4*)(bq + ty * 4);
    float4 bkv = *(const float4*)(bk + ty * 4);
    float bq4[4] = {bqv.x, bqv.y, bqv.z, bqv.w};
    float bk4[4] = {bkv.x, bkv.y, bkv.z, bkv.w};
    const size_t ob = (size_t)b * NPX * CQ;
#pragma unroll
    for (int j = 0; j < 4; j++) {
        const int n = n0 + tx * 4 + j;
        const size_t ofs = ob + (size_t)n * CQ + ty * 4;
        {
            float v0 = aq[0][j] + bq4[0], v1 = aq[1][j] + bq4[1];
            float v2 = aq[2][j] + bq4[2], v3 = aq[3][j] + bq4[3];
            float h0 = __bfloat162float(__float2bfloat16(v0));
            float h1 = __bfloat162float(__float2bfloat16(v1));
            float h2 = __bfloat162float(__float2bfloat16(v2));
            float h3 = __bfloat162float(__float2bfloat16(v3));
            *(uint2*)(qH + ofs) = make_uint2(pack_bf16x2(h0, h1), pack_bf16x2(h2, h3));
            *(uint2*)(qL + ofs) = make_uint2(pack_bf16x2(v0 - h0, v1 - h1),
                                             pack_bf16x2(v2 - h2, v3 - h3));
        }
        {
            float v0 = ak[0][j] + bk4[0], v1 = ak[1][j] + bk4[1];
            float v2 = ak[2][j] + bk4[2], v3 = ak[3][j] + bk4[3];
            float h0 = __bfloat162float(__float2bfloat16(v0));
            float h1 = __bfloat162float(__float2bfloat16(v1));
            float h2 = __bfloat162float(__float2bfloat16(v2));
            float h3 = __bfloat162float(__float2bfloat16(v3));
            *(uint2*)(kH + ofs) = make_uint2(pack_bf16x2(h0, h1), pack_bf16x2(h2, h3));
            *(uint2*)(kL + ofs) = make_uint2(pack_bf16x2(v0 - h0, v1 - h1),
                                             pack_bf16x2(v2 - h2, v3 - h3));
        }
    }
}

// ---------------------------------------------------------------------------
// Kernel 2 (tensor cores, pre-split bf16): E[i][j] = qh*kh + qh*kl + ql*kh
// CTA tile 128x128, FULL K=64 resident in 64KB dynamic smem (128B pitch).
// Single batch per launch (L2 interleave with softmax). [round-13 proven]
// ---------------------------------------------------------------------------
#define E_MAT   (128 * 128)          // 16 KB per matrix
#define E_SMEM  (4 * E_MAT)          // 64 KB

__global__ void __launch_bounds__(256, 2) energy_mma_kernel(float* __restrict__ E,
                                                            int b)
{
    extern __shared__ __align__(128) uint8_t es[];

    const int i0 = blockIdx.y * 128;
    const int j0 = blockIdx.x * 128;
    const int tid = threadIdx.x;
    const int lane = tid & 31;
    const int wid = tid >> 5;
    const int warp_m = (wid & 1) * 64;      // 2 M groups of 64
    const int warp_n = (wid >> 1) * 32;     // 4 N groups of 32

    const __nv_bfloat16* Qh = g_Qh + (size_t)b * NPX * CQ;
    const __nv_bfloat16* Ql = g_Ql + (size_t)b * NPX * CQ;
    const __nv_bfloat16* Kh = g_Kh + (size_t)b * NPX * CQ;
    const __nv_bfloat16* Kl = g_Kl + (size_t)b * NPX * CQ;

    const uint32_t qh_u = smem_u32(es);
    const uint32_t ql_u = qh_u + E_MAT;
    const uint32_t kh_u = qh_u + 2 * E_MAT;
    const uint32_t kl_u = qh_u + 3 * E_MAT;

#pragma unroll
    for (int c = 0; c < 2; c++) {
#pragma unroll
        for (int i = 0; i < 2; i++) {
            const int idx = tid + i * 256;            // 0..511
            const int row = idx >> 2;                 // 0..127
            const int u   = (idx & 3) + c * 4;        // 16B unit 0..7
            const uint32_t off = swz128(row, u);
            const size_t qo = (size_t)(i0 + row) * CQ + u * 8;
            const size_t ko = (size_t)(j0 + row) * CQ + u * 8;
            cp_async16(qh_u + off, Qh + qo);
            cp_async16(ql_u + off, Ql + qo);
            cp_async16(kh_u + off, Kh + ko);
            cp_async16(kl_u + off, Kl + ko);
        }
        CP_COMMIT();
    }

    float acc[4][4][4];
#pragma unroll
    for (int mi = 0; mi < 4; mi++)
#pragma unroll
        for (int ni = 0; ni < 4; ni++)
#pragma unroll
            for (int q = 0; q < 4; q++) acc[mi][ni][q] = 0.f;

    CP_WAIT1();
    __syncthreads();

#pragma unroll
    for (int ks = 0; ks < 4; ks++) {
        if (ks == 2) {
            CP_WAIT0();
            __syncthreads();
        }
        uint32_t ah[4][4];
#pragma unroll
        for (int mi = 0; mi < 4; mi++) {
            const int row = warp_m + mi * 16 + (lane & 7) + ((lane >> 3) & 1) * 8;
            const int u = ks * 2 + (lane >> 4);
            ldmatrix_x4(ah[mi][0], ah[mi][1], ah[mi][2], ah[mi][3],
                        qh_u + swz128(row, u));
        }
        uint32_t bh[4][2], bl[4][2];
#pragma unroll
        for (int ng = 0; ng < 2; ng++) {
            const int row = warp_n + ng * 16 + (lane & 7) + ((lane >> 4) & 1) * 8;
            const int u = ks * 2 + ((lane >> 3) & 1);
            uint32_t r0, r1, r2, r3;
            ldmatrix_x4(r0, r1, r2, r3, kh_u + swz128(row, u));
            bh[ng * 2 + 0][0] = r0; bh[ng * 2 + 0][1] = r1;
            bh[ng * 2 + 1][0] = r2; bh[ng * 2 + 1][1] = r3;
            ldmatrix_x4(r0, r1, r2, r3, kl_u + swz128(row, u));
            bl[ng * 2 + 0][0] = r0; bl[ng * 2 + 0][1] = r1;
            bl[ng * 2 + 1][0] = r2; bl[ng * 2 + 1][1] = r3;
        }
#pragma unroll
        for (int mi = 0; mi < 4; mi++)
#pragma unroll
            for (int ni = 0; ni < 4; ni++) {
                mma_16816(acc[mi][ni], ah[mi][0], ah[mi][1], ah[mi][2], ah[mi][3],
                          bh[ni][0], bh[ni][1]);
                mma_16816(acc[mi][ni], ah[mi][0], ah[mi][1], ah[mi][2], ah[mi][3],
                          bl[ni][0], bl[ni][1]);
            }
        uint32_t al[4][4];
#pragma unroll
        for (int mi = 0; mi < 4; mi++) {
            const int row = warp_m + mi * 16 + (lane & 7) + ((lane >> 3) & 1) * 8;
            const int u = ks * 2 + (lane >> 4);
            ldmatrix_x4(al[mi][0], al[mi][1], al[mi][2], al[mi][3],
                        ql_u + swz128(row, u));
        }
#pragma unroll
        for (int mi = 0; mi < 4; mi++)
#pragma unroll
            for (int ni = 0; ni < 4; ni++)
                mma_16816(acc[mi][ni], al[mi][0], al[mi][1], al[mi][2], al[mi][3],
                          bh[ni][0], bh[ni][1]);
    }

    float* Eb = E + (size_t)b * NPX * NPX;
#pragma unroll
    for (int mi = 0; mi < 4; mi++) {
        const int r0 = i0 + warp_m + mi * 16 + (lane >> 2);
#pragma unroll
        for (int ni = 0; ni < 4; ni++) {
            const int j = j0 + warp_n + ni * 8 + (lane & 3) * 2;
            *(float2*)(Eb + (size_t)r0 * NPX + j) =
                make_float2(acc[mi][ni][0], acc[mi][ni][1]);
            *(float2*)(Eb + (size_t)(r0 + 8) * NPX + j) =
                make_float2(acc[mi][ni][2], acc[mi][ni][3]);
        }
    }
}

// ---------------------------------------------------------------------------
// Kernel 3: row softmax in place + bf16 copy. One block per row; per-batch
// pointers so E reads hit L2 right after energy(b). [round-13 proven]
// ---------------------------------------------------------------------------
__global__ void softmax_kernel(float* __restrict__ attn,
                               __nv_bfloat16* __restrict__ attn_b)
{
    __shared__ float red[8];
    const size_t row = blockIdx.x;
    float* r = attn + row * NPX;
    __nv_bfloat16* rb = attn_b + row * NPX;
    const int t = threadIdx.x;
    const int lane = t & 31;
    const int warp = t >> 5;

    float4 v[4];
#pragma unroll
    for (int u = 0; u < 4; u++)
        v[u] = *(const float4*)(r + (size_t)(t + u * 256) * 4);

    float mx = -3.402823e38f;
#pragma unroll
    for (int u = 0; u < 4; u++)
        mx = fmaxf(mx, fmaxf(fmaxf(v[u].x, v[u].y), fmaxf(v[u].z, v[u].w)));
#pragma unroll
    for (int o = 16; o > 0; o >>= 1)
        mx = fmaxf(mx, __shfl_xor_sync(0xFFFFFFFFu, mx, o));
    if (lane == 0) red[warp] = mx;
    __syncthreads();
    float rowmax = red[0];
#pragma unroll
    for (int u = 1; u < 8; u++) rowmax = fmaxf(rowmax, red[u]);
    __syncthreads();

    float s = 0.f;
#pragma unroll
    for (int u = 0; u < 4; u++) {
        v[u].x = __expf(v[u].x - rowmax);
        v[u].y = __expf(v[u].y - rowmax);
        v[u].z = __expf(v[u].z - rowmax);
        v[u].w = __expf(v[u].w - rowmax);
        s += v[u].x + v[u].y + v[u].z + v[u].w;
    }
#pragma unroll
    for (int o = 16; o > 0; o >>= 1)
        s += __shfl_xor_sync(0xFFFFFFFFu, s, o);
    if (lane == 0) red[warp] = s;
    __syncthreads();
    float total = 0.f;
#pragma unroll
    for (int u = 0; u < 8; u++) total += red[u];
    float inv = 1.0f / total;

#pragma unroll
    for (int u = 0; u < 4; u++) {
        v[u].x *= inv; v[u].y *= inv; v[u].z *= inv; v[u].w *= inv;
        *(float4*)(r + (size_t)(t + u * 256) * 4) = v[u];
        *(uint2*)(rb + (size_t)(t + u * 256) * 4) =
            make_uint2(pack_bf16x2(v[u].x, v[u].y), pack_bf16x2(v[u].z, v[u].w));
    }
}

// ---------------------------------------------------------------------------
// Kernel 4 (mma.sync bf16 + 4-stage cp.async): out = gamma*(xb @ attn_b^T) + x
// CTA tile: M=256 x N=128, 256 threads, 8 warps in 4(M)x2(N); warp tile
// 64x64 -> MMA:LDSM ratio 4 (was 2.67). 128 acc regs/thread, 1 CTA/SM,
// single wave (128 CTAs). Depth-4 cp.async, wait_group 2.
// ---------------------------------------------------------------------------
#define KC       32
#define NKCHUNK  (NPX / KC)                 // 128
#define STG_A    (256 * 64)                 // 16 KB
#define STG_B    (128 * 64)                 // 8 KB
#define STG_SZ   (STG_A + STG_B)            // 24 KB
#define NSTG     4
#define OUT_SMEM (NSTG * STG_SZ)            // 96 KB

__global__ void __launch_bounds__(256, 1)
out_mma_kernel(const float* __restrict__ x,
               const __nv_bfloat16* __restrict__ xb,
               const __nv_bfloat16* __restrict__ attn_b,
               const float* __restrict__ gamma,
               float* __restrict__ outp)
{
    extern __shared__ __align__(128) uint8_t oStg[];

    const int b  = blockIdx.y;
    const int m0 = blockIdx.x * 128;
    const int tid = threadIdx.x;
    const int lane = tid & 31;
    const int wid = tid >> 5;
    const int warp_m = (wid & 3) * 64;      // 4 M groups of 64 rows
    const int warp_n = (wid >> 2) * 64;     // 2 N groups of 64 cols

    const float* A = x + (size_t)b * CCH * NPX;                  // fp32 (epilogue)
    const __nv_bfloat16* Ab = xb + (size_t)b * CCH * NPX;        // [256][4096]
    const __nv_bfloat16* Bb = attn_b + (size_t)b * NPX * NPX;    // [4096][4096]

    const uint32_t stg_u = smem_u32(oStg);

    // loaders: A 1024 x16B units (4/thread), B 512 units (2/thread)
    const int arow = tid >> 2;             // 0..63 (A rows arow + i*64)
    const int aunit = tid & 3;

    float acc[4][8][4];
#pragma unroll
    for (int mi = 0; mi < 4; mi++)
#pragma unroll
        for (int ni = 0; ni < 8; ni++)
#pragma unroll
            for (int q = 0; q < 4; q++) acc[mi][ni][q] = 0.f;

    auto issue_chunk = [&](int kc, int s) {
        const uint32_t base = stg_u + (uint32_t)s * STG_SZ;
        const int k0 = kc * KC;
#pragma unroll
        for (int i = 0; i < 4; i++) {
            const int row = arow + i * 64;
            cp_async16(base + swz16(row, aunit),
                       Ab + (size_t)row * NPX + k0 + aunit * 8);
        }
#pragma unroll
        for (int i = 0; i < 2; i++) {
            const int idx = tid + i * 256;          // 0..511
            const int row = idx >> 2;               // 0..127
            const int u   = idx & 3;
            cp_async16(base + STG_A + swz16(row, u),
                       Bb + (size_t)(m0 + row) * NPX + k0 + u * 8);
        }
        CP_COMMIT();
    };

    issue_chunk(0, 0);
    issue_chunk(1, 1);
    issue_chunk(2, 2);

    for (int kc = 0; kc < NKCHUNK; kc++) {
        const int s = kc & (NSTG - 1);
        CP_WAIT2();
        __syncthreads();
        if (kc + 3 < NKCHUNK) issue_chunk(kc + 3, (kc + 3) & (NSTG - 1));

        const uint32_t aBase = stg_u + (uint32_t)s * STG_SZ;
        const uint32_t bBase = aBase + STG_A;
#pragma unroll
        for (int kk = 0; kk < 2; kk++) {
            uint32_t afr[4][4];
#pragma unroll
            for (int mi = 0; mi < 4; mi++) {
                const int row = warp_m + mi * 16 + (lane & 7) + ((lane >> 3) & 1) * 8;
                const uint32_t chunk = (uint32_t)(kk * 2 + (lane >> 4));
                const uint32_t addr = aBase + (uint32_t)row * 64
                    + ((chunk ^ (((uint32_t)row >> 1) & 3u)) * 16);
                ldmatrix_x4(afr[mi][0], afr[mi][1], afr[mi][2], afr[mi][3], addr);
            }
            uint32_t bfr[8][2];
#pragma unroll
            for (int ng = 0; ng < 4; ng++) {
                const int row = warp_n + ng * 16 + (lane & 7) + ((lane >> 4) & 1) * 8;
                const uint32_t chunk = (uint32_t)(kk * 2 + ((lane >> 3) & 1));
                const uint32_t addr = bBase + (uint32_t)row * 64
                    + ((chunk ^ (((uint32_t)row >> 1) & 3u)) * 16);
                uint32_t r0, r1, r2, r3;
                ldmatrix_x4(r0, r1, r2, r3, addr);
                bfr[ng * 2 + 0][0] = r0; bfr[ng * 2 + 0][1] = r1;
                bfr[ng * 2 + 1][0] = r2; bfr[ng * 2 + 1][1] = r3;
            }
#pragma unroll
            for (int mi = 0; mi < 4; mi++)
#pragma unroll
                for (int ni = 0; ni < 8; ni++)
                    mma_16816(acc[mi][ni], afr[mi][0], afr[mi][1],
                              afr[mi][2], afr[mi][3],
                              bfr[ni][0], bfr[ni][1]);
        }
    }

    // ---- epilogue: out = gamma*acc + x (fp32 residual)
    const float g = gamma[0];
    float* ob = outp + (size_t)b * CCH * NPX;
#pragma unroll
    for (int mi = 0; mi < 4; mi++) {
        const int c0 = warp_m + mi * 16 + (lane >> 2);
#pragma unroll
        for (int ni = 0; ni < 8; ni++) {
            const int m = m0 + warp_n + ni * 8 + (lane & 3) * 2;
            {
                const float2 xv = *(const float2*)(A + (size_t)c0 * NPX + m);
                float2 v = make_float2(fmaf(g, acc[mi][ni][0], xv.x),
                                       fmaf(g, acc[mi][ni][1], xv.y));
                *(float2*)(ob + (size_t)c0 * NPX + m) = v;
            }
            {
                const int c1 = c0 + 8;
                const float2 xv = *(const float2*)(A + (size_t)c1 * NPX + m);
                float2 v = make_float2(fmaf(g, acc[mi][ni][2], xv.x),
                                       fmaf(g, acc[mi][ni][3], xv.y));
                *(float2*)(ob + (size_t)c1 * NPX + m) = v;
            }
        }
    }
}

// ---------------------------------------------------------------------------
// Launch: per-batch energy->softmax interleave (round-13 proven structure).
// ---------------------------------------------------------------------------
extern "C" void kernel_launch(void* const* d_in, const int* in_sizes, int n_in,
                              void* d_out, int out_size)
{
    const float* x     = (const float*)d_in[0];
    const float* w_q   = (const float*)d_in[1];
    const float* b_q   = (const float*)d_in[2];
    const float* w_k   = (const float*)d_in[3];
    const float* b_k   = (const float*)d_in[4];
    const float* gamma = (const float*)d_in[5];

    float* outp = (float*)d_out;

    float* attn;
    if ((size_t)out_size >= OUT_ELEMS + ATTN_ELEMS) {
        attn = outp + OUT_ELEMS;
    } else {
        void* p = nullptr;
        cudaGetSymbolAddress(&p, g_attn_fb);
        attn = (float*)p;
    }

    void *pqh = nullptr, *pql = nullptr, *pkh = nullptr, *pkl = nullptr;
    void *pxb = nullptr, *pab = nullptr;
    cudaGetSymbolAddress(&pqh, g_Qh);
    cudaGetSymbolAddress(&pql, g_Ql);
    cudaGetSymbolAddress(&pkh, g_Kh);
    cudaGetSymbolAddress(&pkl, g_Kl);
    cudaGetSymbolAddress(&pxb, g_Xb);
    cudaGetSymbolAddress(&pab, g_attn_b);

    static int smem_set = 0;
    if (!smem_set) {
        cudaFuncSetAttribute(energy_mma_kernel,
                             cudaFuncAttributeMaxDynamicSharedMemorySize, E_SMEM);
        cudaFuncSetAttribute(out_mma_kernel,
                             cudaFuncAttributeMaxDynamicSharedMemorySize, OUT_SMEM);
        smem_set = 1;
    }

    dim3 gp(NPX / 64, BB);
    proj2_kernel<<<gp, 256>>>(x, w_q, b_q, w_k, b_k,
                              (__nv_bfloat16*)pqh, (__nv_bfloat16*)pql,
                              (__nv_bfloat16*)pkh, (__nv_bfloat16*)pkl);

    xconv_kernel<<<2048, 256>>>(x, (__nv_bfloat16*)pxb);

    dim3 ge(NPX / 128, NPX / 128);
    for (int b = 0; b < BB; b++) {
        energy_mma_kernel<<<ge, 256, E_SMEM>>>(attn, b);
        softmax_kernel<<<NPX, 256>>>(attn + (size_t)b * NPX * NPX,
                                     (__nv_bfloat16*)pab + (size_t)b * NPX * NPX);
    }

    dim3 go(NPX / 128, BB);
    out_mma_kernel<<<go, 256, OUT_SMEM>>>(x, (const __nv_bfloat16*)pxb,
                                          (const __nv_bfloat16*)pab, gamma, outp);
}

// round 17
// speedup vs baseline: 1.2130x; 1.0498x over previous
#include <cuda_runtime.h>
#include <cuda_fp16.h>
#include <cstdint>

// Problem constants
#define BB   4
#define CCH  256
#define NPX  4096     // W*H = 64*64
#define CQ   64       // C/4

#define OUT_ELEMS  ((size_t)BB * CCH * NPX)          // 4,194,304
#define ATTN_ELEMS ((size_t)BB * NPX * NPX)          // 67,108,864

// Scratch: fp16 split Q (hi+lo) and K (hi only); fp16 x; fp16 attn
__device__ __half g_Qh[BB * NPX * CQ];
__device__ __half g_Ql[BB * NPX * CQ];
__device__ __half g_Kh[BB * NPX * CQ];
__device__ __half g_Xh[BB * CCH * NPX];
__device__ __half g_attn_h[ATTN_ELEMS];
// Fallback attention buffer in case d_out only holds `out`
__device__ float g_attn_fb[ATTN_ELEMS];

// ===========================================================================
// Helpers (base sm_100-legal: ldmatrix + mma.sync + cp.async)
// ===========================================================================
__device__ __forceinline__ uint32_t smem_u32(const void* p) {
    uint32_t a;
    asm("{ .reg .u64 t; cvta.to.shared.u64 t, %1; cvt.u32.u64 %0, t; }"
        : "=r"(a) : "l"(p));
    return a;
}
// Pack two f32 into f16x2 {lo, hi}. Single SASS op.
__device__ __forceinline__ uint32_t pack_f16x2(float lo, float hi) {
    uint32_t r;
    asm("cvt.rn.f16x2.f32 %0, %1, %2;" : "=r"(r) : "f"(hi), "f"(lo));
    return r;
}
__device__ __forceinline__ void ldmatrix_x4(uint32_t& r0, uint32_t& r1,
                                            uint32_t& r2, uint32_t& r3,
                                            uint32_t addr) {
    asm volatile("ldmatrix.sync.aligned.m8n8.x4.shared.b16 {%0,%1,%2,%3}, [%4];"
                 : "=r"(r0), "=r"(r1), "=r"(r2), "=r"(r3) : "r"(addr));
}
__device__ __forceinline__ void mma_16816(float* c, uint32_t a0, uint32_t a1,
                                          uint32_t a2, uint32_t a3,
                                          uint32_t b0, uint32_t b1) {
    asm volatile(
        "mma.sync.aligned.m16n8k16.row.col.f32.f16.f16.f32 "
        "{%0,%1,%2,%3}, {%4,%5,%6,%7}, {%8,%9}, {%0,%1,%2,%3};"
        : "+f"(c[0]), "+f"(c[1]), "+f"(c[2]), "+f"(c[3])
        : "r"(a0), "r"(a1), "r"(a2), "r"(a3), "r"(b0), "r"(b1));
}
__device__ __forceinline__ void cp_async16(uint32_t smem_addr, const void* gptr) {
    asm volatile("cp.async.cg.shared.global [%0], [%1], 16;"
                 :: "r"(smem_addr), "l"(gptr));
}
#define CP_COMMIT() asm volatile("cp.async.commit_group;")
#define CP_WAIT0()  asm volatile("cp.async.wait_group 0;")
#define CP_WAIT1()  asm volatile("cp.async.wait_group 1;")
#define CP_WAIT2()  asm volatile("cp.async.wait_group 2;")

// 64B-pitch swizzle (16B units 0..3)
__device__ __forceinline__ uint32_t swz16(int row, int unit) {
    return (uint32_t)row * 64 + (((uint32_t)unit ^ (((uint32_t)row >> 1) & 3u)) * 16);
}
// 128B-pitch swizzle (16B units 0..7)
__device__ __forceinline__ uint32_t swz128(int row, int unit) {
    return (uint32_t)row * 128 + (((uint32_t)unit ^ ((uint32_t)row & 7u)) * 16);
}

// ---------------------------------------------------------------------------
// Kernel 0: x -> fp16 copy
// ---------------------------------------------------------------------------
__global__ void xconv_kernel(const float* __restrict__ x, __half* __restrict__ xh)
{
    const size_t n4 = OUT_ELEMS / 4;
    for (size_t i = (size_t)blockIdx.x * blockDim.x + threadIdx.x; i < n4;
         i += (size_t)gridDim.x * blockDim.x) {
        float4 v = *(const float4*)(x + i * 4);
        *(uint2*)(xh + i * 4) = make_uint2(pack_f16x2(v.x, v.y),
                                           pack_f16x2(v.z, v.w));
    }
}

// ---------------------------------------------------------------------------
// Kernel 1: fused Q+K projection. Q split into fp16 hi/lo (exact sum),
// K stored as fp16 hi only (2-term energy uses q * kh).
// ---------------------------------------------------------------------------
__global__ void proj2_kernel(const float* __restrict__ x,
                             const float* __restrict__ wq,
                             const float* __restrict__ bq,
                             const float* __restrict__ wk,
                             const float* __restrict__ bk,
                             __half* __restrict__ qH,
                             __half* __restrict__ qL,
                             __half* __restrict__ kH)
{
    const int b  = blockIdx.y;
    const int n0 = blockIdx.x * 64;
    const int tid = threadIdx.x;
    const int tx = tid & 15;        // n dimension
    const int ty = tid >> 4;        // oc dimension

    __shared__ __align__(16) float Xs[32][64];    // [c][n]
    __shared__ __align__(16) float Wq[32][68];    // [c][oc]
    __shared__ __align__(16) float Wk[32][68];    // [c][oc]

    const float* xb = x + (size_t)b * CCH * NPX;

    float aq[4][4], ak[4][4];
#pragma unroll
    for (int i = 0; i < 4; i++)
#pragma unroll
        for (int j = 0; j < 4; j++) { aq[i][j] = 0.f; ak[i][j] = 0.f; }

    for (int c0 = 0; c0 < CCH; c0 += 32) {
#pragma unroll
        for (int r = 0; r < 2; r++) {
            int idx = tid + r * 256;
            int cc  = idx >> 4;
            int nq  = (idx & 15) << 2;
            float4 v = *(const float4*)(xb + (size_t)(c0 + cc) * NPX + n0 + nq);
            *(float4*)(&Xs[cc][nq]) = v;
        }
#pragma unroll
        for (int r = 0; r < 2; r++) {
            int idx = tid + r * 256;
            int oc  = idx >> 3;
            int cq  = (idx & 7) << 2;
            float4 v = *(const float4*)(wq + oc * CCH + c0 + cq);
            Wq[cq + 0][oc] = v.x; Wq[cq + 1][oc] = v.y;
            Wq[cq + 2][oc] = v.z; Wq[cq + 3][oc] = v.w;
            float4 u = *(const float4*)(wk + oc * CCH + c0 + cq);
            Wk[cq + 0][oc] = u.x; Wk[cq + 1][oc] = u.y;
            Wk[cq + 2][oc] = u.z; Wk[cq + 3][oc] = u.w;
        }
        __syncthreads();
#pragma unroll
        for (int cc = 0; cc < 32; cc++) {
            float4 q4 = *(const float4*)(&Wq[cc][ty * 4]);
            float4 k4 = *(const float4*)(&Wk[cc][ty * 4]);
            float4 bv = *(const float4*)(&Xs[cc][tx * 4]);
            float qv[4] = {q4.x, q4.y, q4.z, q4.w};
            float kv[4] = {k4.x, k4.y, k4.z, k4.w};
            float bw[4] = {bv.x, bv.y, bv.z, bv.w};
#pragma unroll
            for (int i = 0; i < 4; i++)
#pragma unroll
                for (int j = 0; j < 4; j++) {
                    aq[i][j] = fmaf(qv[i], bw[j], aq[i][j]);
                    ak[i][j] = fmaf(kv[i], bw[j], ak[i][j]);
                }
        }
        __syncthreads();
    }

    float4 bqv = *(const float4*)(bq + ty * 4);
    float4 bkv = *(const float4*)(bk + ty * 4);
    float bq4[4] = {bqv.x, bqv.y, bqv.z, bqv.w};
    float bk4[4] = {bkv.x, bkv.y, bkv.z, bkv.w};
    const size_t ob = (size_t)b * NPX * CQ;
#pragma unroll
    for (int j = 0; j < 4; j++) {
        const int n = n0 + tx * 4 + j;
        const size_t ofs = ob + (size_t)n * CQ + ty * 4;
        {
            float v0 = aq[0][j] + bq4[0], v1 = aq[1][j] + bq4[1];
            float v2 = aq[2][j] + bq4[2], v3 = aq[3][j] + bq4[3];
            float h0 = __half2float(__float2half_rn(v0));
            float h1 = __half2float(__float2half_rn(v1));
            float h2 = __half2float(__float2half_rn(v2));
            float h3 = __half2float(__float2half_rn(v3));
            *(uint2*)(qH + ofs) = make_uint2(pack_f16x2(h0, h1), pack_f16x2(h2, h3));
            *(uint2*)(qL + ofs) = make_uint2(pack_f16x2(v0 - h0, v1 - h1),
                                             pack_f16x2(v2 - h2, v3 - h3));
        }
        {
            float v0 = ak[0][j] + bk4[0], v1 = ak[1][j] + bk4[1];
            float v2 = ak[2][j] + bk4[2], v3 = ak[3][j] + bk4[3];
            *(uint2*)(kH + ofs) = make_uint2(pack_f16x2(v0, v1), pack_f16x2(v2, v3));
        }
    }
}

// ---------------------------------------------------------------------------
// Kernel 2 (tensor cores, fp16 2-term): E[i][j] = (qh + ql) . kh  = q . kh
// CTA tile 128x128, FULL K=64 resident in 48KB dynamic smem (128B pitch).
// 8 MMAs per warp-ks (was 12). Single batch per launch (L2 interleave).
// ---------------------------------------------------------------------------
#define E_MAT   (128 * 128)          // 16 KB per matrix
#define E_SMEM  (3 * E_MAT)          // 48 KB

__global__ void __launch_bounds__(256, 2) energy_mma_kernel(float* __restrict__ E,
                                                            int b)
{
    extern __shared__ __align__(128) uint8_t es[];

    const int i0 = blockIdx.y * 128;
    const int j0 = blockIdx.x * 128;
    const int tid = threadIdx.x;
    const int lane = tid & 31;
    const int wid = tid >> 5;
    const int warp_m = (wid & 1) * 64;      // 2 M groups of 64
    const int warp_n = (wid >> 1) * 32;     // 4 N groups of 32

    const __half* Qh = g_Qh + (size_t)b * NPX * CQ;
    const __half* Ql = g_Ql + (size_t)b * NPX * CQ;
    const __half* Kh = g_Kh + (size_t)b * NPX * CQ;

    const uint32_t qh_u = smem_u32(es);
    const uint32_t ql_u = qh_u + E_MAT;
    const uint32_t kh_u = qh_u + 2 * E_MAT;

#pragma unroll
    for (int c = 0; c < 2; c++) {
#pragma unroll
        for (int i = 0; i < 2; i++) {
            const int idx = tid + i * 256;            // 0..511
            const int row = idx >> 2;                 // 0..127
            const int u   = (idx & 3) + c * 4;        // 16B unit 0..7
            const uint32_t off = swz128(row, u);
            const size_t qo = (size_t)(i0 + row) * CQ + u * 8;
            const size_t ko = (size_t)(j0 + row) * CQ + u * 8;
            cp_async16(qh_u + off, Qh + qo);
            cp_async16(ql_u + off, Ql + qo);
            cp_async16(kh_u + off, Kh + ko);
        }
        CP_COMMIT();
    }

    float acc[4][4][4];
#pragma unroll
    for (int mi = 0; mi < 4; mi++)
#pragma unroll
        for (int ni = 0; ni < 4; ni++)
#pragma unroll
            for (int q = 0; q < 4; q++) acc[mi][ni][q] = 0.f;

    CP_WAIT1();
    __syncthreads();

#pragma unroll
    for (int ks = 0; ks < 4; ks++) {
        if (ks == 2) {
            CP_WAIT0();
            __syncthreads();
        }
        uint32_t ah[4][4];
#pragma unroll
        for (int mi = 0; mi < 4; mi++) {
            const int row = warp_m + mi * 16 + (lane & 7) + ((lane >> 3) & 1) * 8;
            const int u = ks * 2 + (lane >> 4);
            ldmatrix_x4(ah[mi][0], ah[mi][1], ah[mi][2], ah[mi][3],
                        qh_u + swz128(row, u));
        }
        uint32_t bh[4][2];
#pragma unroll
        for (int ng = 0; ng < 2; ng++) {
            const int row = warp_n + ng * 16 + (lane & 7) + ((lane >> 4) & 1) * 8;
            const int u = ks * 2 + ((lane >> 3) & 1);
            uint32_t r0, r1, r2, r3;
            ldmatrix_x4(r0, r1, r2, r3, kh_u + swz128(row, u));
            bh[ng * 2 + 0][0] = r0; bh[ng * 2 + 0][1] = r1;
            bh[ng * 2 + 1][0] = r2; bh[ng * 2 + 1][1] = r3;
        }
#pragma unroll
        for (int mi = 0; mi < 4; mi++)
#pragma unroll
            for (int ni = 0; ni < 4; ni++)
                mma_16816(acc[mi][ni], ah[mi][0], ah[mi][1], ah[mi][2], ah[mi][3],
                          bh[ni][0], bh[ni][1]);
        uint32_t al[4][4];
#pragma unroll
        for (int mi = 0; mi < 4; mi++) {
            const int row = warp_m + mi * 16 + (lane & 7) + ((lane >> 3) & 1) * 8;
            const int u = ks * 2 + (lane >> 4);
            ldmatrix_x4(al[mi][0], al[mi][1], al[mi][2], al[mi][3],
                        ql_u + swz128(row, u));
        }
#pragma unroll
        for (int mi = 0; mi < 4; mi++)
#pragma unroll
            for (int ni = 0; ni < 4; ni++)
                mma_16816(acc[mi][ni], al[mi][0], al[mi][1], al[mi][2], al[mi][3],
                          bh[ni][0], bh[ni][1]);
    }

    float* Eb = E + (size_t)b * NPX * NPX;
#pragma unroll
    for (int mi = 0; mi < 4; mi++) {
        const int r0 = i0 + warp_m + mi * 16 + (lane >> 2);
#pragma unroll
        for (int ni = 0; ni < 4; ni++) {
            const int j = j0 + warp_n + ni * 8 + (lane & 3) * 2;
            *(float2*)(Eb + (size_t)r0 * NPX + j) =
                make_float2(acc[mi][ni][0], acc[mi][ni][1]);
            *(float2*)(Eb + (size_t)(r0 + 8) * NPX + j) =
                make_float2(acc[mi][ni][2], acc[mi][ni][3]);
        }
    }
}

// ---------------------------------------------------------------------------
// Kernel 3: row softmax in place + fp16 copy. One block per row; per-batch
// pointers so E reads hit L2 right after energy(b).
// ---------------------------------------------------------------------------
__global__ void softmax_kernel(float* __restrict__ attn,
                               __half* __restrict__ attn_h)
{
    __shared__ float red[8];
    const size_t row = blockIdx.x;
    float* r = attn + row * NPX;
    __half* rh = attn_h + row * NPX;
    const int t = threadIdx.x;
    const int lane = t & 31;
    const int warp = t >> 5;

    float4 v[4];
#pragma unroll
    for (int u = 0; u < 4; u++)
        v[u] = *(const float4*)(r + (size_t)(t + u * 256) * 4);

    float mx = -3.402823e38f;
#pragma unroll
    for (int u = 0; u < 4; u++)
        mx = fmaxf(mx, fmaxf(fmaxf(v[u].x, v[u].y), fmaxf(v[u].z, v[u].w)));
#pragma unroll
    for (int o = 16; o > 0; o >>= 1)
        mx = fmaxf(mx, __shfl_xor_sync(0xFFFFFFFFu, mx, o));
    if (lane == 0) red[warp] = mx;
    __syncthreads();
    float rowmax = red[0];
#pragma unroll
    for (int u = 1; u < 8; u++) rowmax = fmaxf(rowmax, red[u]);
    __syncthreads();

    float s = 0.f;
#pragma unroll
    for (int u = 0; u < 4; u++) {
        v[u].x = __expf(v[u].x - rowmax);
        v[u].y = __expf(v[u].y - rowmax);
        v[u].z = __expf(v[u].z - rowmax);
        v[u].w = __expf(v[u].w - rowmax);
        s += v[u].x + v[u].y + v[u].z + v[u].w;
    }
#pragma unroll
    for (int o = 16; o > 0; o >>= 1)
        s += __shfl_xor_sync(0xFFFFFFFFu, s, o);
    if (lane == 0) red[warp] = s;
    __syncthreads();
    float total = 0.f;
#pragma unroll
    for (int u = 0; u < 8; u++) total += red[u];
    float inv = 1.0f / total;

#pragma unroll
    for (int u = 0; u < 4; u++) {
        v[u].x *= inv; v[u].y *= inv; v[u].z *= inv; v[u].w *= inv;
        *(float4*)(r + (size_t)(t + u * 256) * 4) = v[u];
        *(uint2*)(rh + (size_t)(t + u * 256) * 4) =
            make_uint2(pack_f16x2(v[u].x, v[u].y), pack_f16x2(v[u].z, v[u].w));
    }
}

// ---------------------------------------------------------------------------
// Kernel 4 (mma.sync fp16 + 4-stage cp.async): out = gamma*(xh @ attn_h^T) + x
// CTA tile: M=256 x N=128, 256 threads, 8 warps in 4(M)x2(N); warp 64x64.
// Depth-4 cp.async, wait_group 2.  [round-16 structure, fp16 operands]
// ---------------------------------------------------------------------------
#define KC       32
#define NKCHUNK  (NPX / KC)                 // 128
#define STG_A    (256 * 64)                 // 16 KB
#define STG_B    (128 * 64)                 // 8 KB
#define STG_SZ   (STG_A + STG_B)            // 24 KB
#define NSTG     4
#define OUT_SMEM (NSTG * STG_SZ)            // 96 KB

__global__ void __launch_bounds__(256, 1)
out_mma_kernel(const float* __restrict__ x,
               const __half* __restrict__ xh,
               const __half* __restrict__ attn_h,
               const float* __restrict__ gamma,
               float* __restrict__ outp)
{
    extern __shared__ __align__(128) uint8_t oStg[];

    const int b  = blockIdx.y;
    const int m0 = blockIdx.x * 128;
    const int tid = threadIdx.x;
    const int lane = tid & 31;
    const int wid = tid >> 5;
    const int warp_m = (wid & 3) * 64;      // 4 M groups of 64 rows
    const int warp_n = (wid >> 2) * 64;     // 2 N groups of 64 cols

    const float* A = x + (size_t)b * CCH * NPX;                  // fp32 (epilogue)
    const __half* Ab = xh + (size_t)b * CCH * NPX;               // [256][4096]
    const __half* Bb = attn_h + (size_t)b * NPX * NPX;           // [4096][4096]

    const uint32_t stg_u = smem_u32(oStg);

    const int arow = tid >> 2;             // 0..63 (A rows arow + i*64)
    const int aunit = tid & 3;

    float acc[4][8][4];
#pragma unroll
    for (int mi = 0; mi < 4; mi++)
#pragma unroll
        for (int ni = 0; ni < 8; ni++)
#pragma unroll
            for (int q = 0; q < 4; q++) acc[mi][ni][q] = 0.f;

    auto issue_chunk = [&](int kc, int s) {
        const uint32_t base = stg_u + (uint32_t)s * STG_SZ;
        const int k0 = kc * KC;
#pragma unroll
        for (int i = 0; i < 4; i++) {
            const int row = arow + i * 64;
            cp_async16(base + swz16(row, aunit),
                       Ab + (size_t)row * NPX + k0 + aunit * 8);
        }
#pragma unroll
        for (int i = 0; i < 2; i++) {
            const int idx = tid + i * 256;          // 0..511
            const int row = idx >> 2;               // 0..127
            const int u   = idx & 3;
            cp_async16(base + STG_A + swz16(row, u),
                       Bb + (size_t)(m0 + row) * NPX + k0 + u * 8);
        }
        CP_COMMIT();
    };

    issue_chunk(0, 0);
    issue_chunk(1, 1);
    issue_chunk(2, 2);

    for (int kc = 0; kc < NKCHUNK; kc++) {
        const int s = kc & (NSTG - 1);
        CP_WAIT2();
        __syncthreads();
        if (kc + 3 < NKCHUNK) issue_chunk(kc + 3, (kc + 3) & (NSTG - 1));

        const uint32_t aBase = stg_u + (uint32_t)s * STG_SZ;
        const uint32_t bBase = aBase + STG_A;
#pragma unroll
        for (int kk = 0; kk < 2; kk++) {
            uint32_t afr[4][4];
#pragma unroll
            for (int mi = 0; mi < 4; mi++) {
                const int row = warp_m + mi * 16 + (lane & 7) + ((lane >> 3) & 1) * 8;
                const uint32_t chunk = (uint32_t)(kk * 2 + (lane >> 4));
                const uint32_t addr = aBase + (uint32_t)row * 64
                    + ((chunk ^ (((uint32_t)row >> 1) & 3u)) * 16);
                ldmatrix_x4(afr[mi][0], afr[mi][1], afr[mi][2], afr[mi][3], addr);
            }
            uint32_t bfr[8][2];
#pragma unroll
            for (int ng = 0; ng < 4; ng++) {
                const int row = warp_n + ng * 16 + (lane & 7) + ((lane >> 4) & 1) * 8;
                const uint32_t chunk = (uint32_t)(kk * 2 + ((lane >> 3) & 1));
                const uint32_t addr = bBase + (uint32_t)row * 64
                    + ((chunk ^ (((uint32_t)row >> 1) & 3u)) * 16);
                uint32_t r0, r1, r2, r3;
                ldmatrix_x4(r0, r1, r2, r3, addr);
                bfr[ng * 2 + 0][0] = r0; bfr[ng * 2 + 0][1] = r1;
                bfr[ng * 2 + 1][0] = r2; bfr[ng * 2 + 1][1] = r3;
            }
#pragma unroll
            for (int mi = 0; mi < 4; mi++)
#pragma unroll
                for (int ni = 0; ni < 8; ni++)
                    mma_16816(acc[mi][ni], afr[mi][0], afr[mi][1],
                              afr[mi][2], afr[mi][3],
                              bfr[ni][0], bfr[ni][1]);
        }
    }

    // ---- epilogue: out = gamma*acc + x (fp32 residual)
    const float g = gamma[0];
    float* ob = outp + (size_t)b * CCH * NPX;
#pragma unroll
    for (int mi = 0; mi < 4; mi++) {
        const int c0 = warp_m + mi * 16 + (lane >> 2);
#pragma unroll
        for (int ni = 0; ni < 8; ni++) {
            const int m = m0 + warp_n + ni * 8 + (lane & 3) * 2;
            {
                const float2 xv = *(const float2*)(A + (size_t)c0 * NPX + m);
                float2 v = make_float2(fmaf(g, acc[mi][ni][0], xv.x),
                                       fmaf(g, acc[mi][ni][1], xv.y));
                *(float2*)(ob + (size_t)c0 * NPX + m) = v;
            }
            {
                const int c1 = c0 + 8;
                const float2 xv = *(const float2*)(A + (size_t)c1 * NPX + m);
                float2 v = make_float2(fmaf(g, acc[mi][ni][2], xv.x),
                                       fmaf(g, acc[mi][ni][3], xv.y));
                *(float2*)(ob + (size_t)c1 * NPX + m) = v;
            }
        }
    }
}

// ---------------------------------------------------------------------------
// Launch: per-batch energy->softmax interleave (round-13 proven structure).
// ---------------------------------------------------------------------------
extern "C" void kernel_launch(void* const* d_in, const int* in_sizes, int n_in,
                              void* d_out, int out_size)
{
    const float* x     = (const float*)d_in[0];
    const float* w_q   = (const float*)d_in[1];
    const float* b_q   = (const float*)d_in[2];
    const float* w_k   = (const float*)d_in[3];
    const float* b_k   = (const float*)d_in[4];
    const float* gamma = (const float*)d_in[5];

    float* outp = (float*)d_out;

    float* attn;
    if ((size_t)out_size >= OUT_ELEMS + ATTN_ELEMS) {
        attn = outp + OUT_ELEMS;
    } else {
        void* p = nullptr;
        cudaGetSymbolAddress(&p, g_attn_fb);
        attn = (float*)p;
    }

    void *pqh = nullptr, *pql = nullptr, *pkh = nullptr;
    void *pxh = nullptr, *pah = nullptr;
    cudaGetSymbolAddress(&pqh, g_Qh);
    cudaGetSymbolAddress(&pql, g_Ql);
    cudaGetSymbolAddress(&pkh, g_Kh);
    cudaGetSymbolAddress(&pxh, g_Xh);
    cudaGetSymbolAddress(&pah, g_attn_h);

    static int smem_set = 0;
    if (!smem_set) {
        cudaFuncSetAttribute(energy_mma_kernel,
                             cudaFuncAttributeMaxDynamicSharedMemorySize, E_SMEM);
        cudaFuncSetAttribute(out_mma_kernel,
                             cudaFuncAttributeMaxDynamicSharedMemorySize, OUT_SMEM);
        smem_set = 1;
    }

    dim3 gp(NPX / 64, BB);
    proj2_kernel<<<gp, 256>>>(x, w_q, b_q, w_k, b_k,
                              (__half*)pqh, (__half*)pql, (__half*)pkh);

    xconv_kernel<<<2048, 256>>>(x, (__half*)pxh);

    dim3 ge(NPX / 128, NPX / 128);
    for (int b = 0; b < BB; b++) {
        energy_mma_kernel<<<ge, 256, E_SMEM>>>(attn, b);
        softmax_kernel<<<NPX, 256>>>(attn + (size_t)b * NPX * NPX,
                                     (__half*)pah + (size_t)b * NPX * NPX);
    }

    dim3 go(NPX / 128, BB);
    out_mma_kernel<<<go, 256, OUT_SMEM>>>(x, (const __half*)pxh,
                                          (const __half*)pah, gamma, outp);
}